// round 1
// baseline (speedup 1.0000x reference)
#include <cuda_runtime.h>

#define T_SEQ 2048
#define D_MODEL 1024
#define NH 16
#define HD 64
#define BATCH 4
#define M_TOT (BATCH * T_SEQ)   // 8192

// Scratch (allocation-free requirement -> __device__ globals)
__device__ float g_qkv[(size_t)M_TOT * 3 * D_MODEL];   // 96 MB: [m, 3*1024]
__device__ float g_attn[(size_t)M_TOT * D_MODEL];      // 32 MB: [m, 1024]

// ---------------------------------------------------------------------------
// GEMM: C[M,N] = A[M,K] @ Bmat[N,K]^T + bias[N]   (both operands K-contiguous)
// 128x128x16 tile, 256 threads, 8x8 per thread (split 4+4 fragments at +0/+64
// so float4 smem reads are bank-conflict-free across the warp).
// ---------------------------------------------------------------------------
#define BM 128
#define BN 128
#define BK 16

__global__ __launch_bounds__(256) void gemm_nt_bias(
    const float* __restrict__ A, const float* __restrict__ Bmat,
    const float* __restrict__ bias, float* __restrict__ C,
    int M, int N, int K)
{
    __shared__ float As[BK][BM];
    __shared__ float Bs[BK][BN];

    const int bm = blockIdx.y * BM;
    const int bn = blockIdx.x * BN;
    const int tid = threadIdx.x;
    const int tcol = tid & 15;   // 0..15 -> n fragment
    const int trow = tid >> 4;   // 0..15 -> m fragment

    float acc[8][8];
    #pragma unroll
    for (int i = 0; i < 8; i++)
        #pragma unroll
        for (int j = 0; j < 8; j++)
            acc[i][j] = 0.f;

    const float* Aptr = A + (size_t)bm * K;
    const float* Bptr = Bmat + (size_t)bn * K;

    for (int k0 = 0; k0 < K; k0 += BK) {
        // Load tiles: 512 float4 per operand tile, 2 per thread.
        #pragma unroll
        for (int i = 0; i < 2; i++) {
            int idx = tid + i * 256;          // 0..511
            int row = idx >> 2;               // 0..127
            int kc  = (idx & 3) << 2;         // 0,4,8,12
            float4 a = *(const float4*)(Aptr + (size_t)row * K + k0 + kc);
            As[kc + 0][row] = a.x; As[kc + 1][row] = a.y;
            As[kc + 2][row] = a.z; As[kc + 3][row] = a.w;
            float4 b = *(const float4*)(Bptr + (size_t)row * K + k0 + kc);
            Bs[kc + 0][row] = b.x; Bs[kc + 1][row] = b.y;
            Bs[kc + 2][row] = b.z; Bs[kc + 3][row] = b.w;
        }
        __syncthreads();

        #pragma unroll
        for (int kk = 0; kk < BK; kk++) {
            float ra[8], rb[8];
            *(float4*)&ra[0] = *(const float4*)&As[kk][trow * 4];
            *(float4*)&ra[4] = *(const float4*)&As[kk][trow * 4 + 64];
            *(float4*)&rb[0] = *(const float4*)&Bs[kk][tcol * 4];
            *(float4*)&rb[4] = *(const float4*)&Bs[kk][tcol * 4 + 64];
            #pragma unroll
            for (int i = 0; i < 8; i++)
                #pragma unroll
                for (int j = 0; j < 8; j++)
                    acc[i][j] += ra[i] * rb[j];
        }
        __syncthreads();
    }

    #pragma unroll
    for (int ii = 0; ii < 2; ii++)
        #pragma unroll
        for (int i = 0; i < 4; i++) {
            int m = bm + ii * 64 + trow * 4 + i;
            #pragma unroll
            for (int jj = 0; jj < 2; jj++) {
                int n = bn + jj * 64 + tcol * 4;
                float4 bv = *(const float4*)(bias + n);
                float4 o;
                o.x = acc[ii * 4 + i][jj * 4 + 0] + bv.x;
                o.y = acc[ii * 4 + i][jj * 4 + 1] + bv.y;
                o.z = acc[ii * 4 + i][jj * 4 + 2] + bv.z;
                o.w = acc[ii * 4 + i][jj * 4 + 3] + bv.w;
                *(float4*)(C + (size_t)m * N + n) = o;
            }
        }
}

// ---------------------------------------------------------------------------
// Local windowed attention.
// Block = (32 queries) x (one head) x (one batch). K/V window of 96 keys
// staged in smem. One warp per query; lane = head-dim pair (d, d+32).
// Online softmax with exactly one __expf per key (branch is warp-uniform).
// ---------------------------------------------------------------------------
#define QT 32
#define KT 96   // QT + 2*32

__global__ __launch_bounds__(256) void attn_local(
    const float* __restrict__ qkv, float* __restrict__ out)
{
    __shared__ float Ks[KT][HD];   // 24 KB
    __shared__ float Vs[KT][HD];   // 24 KB

    const int b = blockIdx.z, h = blockIdx.y;
    const int t0 = blockIdx.x * QT;
    const int kbase = t0 - 32;
    const int tid = threadIdx.x;

    // Stage K/V window: 96 rows x 64 cols, float4 -> 1536 loads / 256 thr = 6 each
    #pragma unroll
    for (int i = 0; i < 6; i++) {
        int idx = tid + i * 256;        // < 1536
        int row = idx >> 4;             // 0..95
        int c   = (idx & 15) << 2;      // 0..60
        int tk  = kbase + row;
        if (tk >= 0 && tk < T_SEQ) {
            const float* base = qkv + ((size_t)(b * T_SEQ + tk)) * (3 * D_MODEL) + h * HD;
            *(float4*)&Ks[row][c] = *(const float4*)(base + D_MODEL + c);
            *(float4*)&Vs[row][c] = *(const float4*)(base + 2 * D_MODEL + c);
        }
    }
    __syncthreads();

    const int warp = tid >> 5, lane = tid & 31;
    const float scale = 0.125f;   // 1/sqrt(64)

    #pragma unroll 1
    for (int qq = 0; qq < QT / 8; qq++) {
        int qi = warp * (QT / 8) + qq;      // 0..31
        int t  = t0 + qi;
        const float* qptr = qkv + ((size_t)(b * T_SEQ + t)) * (3 * D_MODEL) + h * HD;
        float q0 = qptr[lane] * scale;
        float q1 = qptr[lane + 32] * scale;

        int jlo = qi;                       // local index of key t-32
        if (kbase + jlo < 0) jlo = -kbase;
        int jhi = qi + 64;                  // local index of key t+32
        if (kbase + jhi > T_SEQ - 1) jhi = T_SEQ - 1 - kbase;

        float m = -1e30f, l = 0.f, a0 = 0.f, a1 = 0.f;
        for (int j = jlo; j <= jhi; j++) {
            float s = q0 * Ks[j][lane] + q1 * Ks[j][lane + 32];
            s += __shfl_xor_sync(0xffffffffu, s, 16);
            s += __shfl_xor_sync(0xffffffffu, s, 8);
            s += __shfl_xor_sync(0xffffffffu, s, 4);
            s += __shfl_xor_sync(0xffffffffu, s, 2);
            s += __shfl_xor_sync(0xffffffffu, s, 1);
            float v0 = Vs[j][lane], v1 = Vs[j][lane + 32];
            if (s > m) {                    // warp-uniform branch
                float corr = __expf(m - s); // first iter: exp(-huge) -> 0
                m = s;
                l  = l  * corr + 1.f;
                a0 = a0 * corr + v0;
                a1 = a1 * corr + v1;
            } else {
                float p = __expf(s - m);
                l  += p;
                a0 += p * v0;
                a1 += p * v1;
            }
        }
        float inv = 1.f / l;
        float* optr = out + ((size_t)(b * T_SEQ + t)) * D_MODEL + h * HD;
        optr[lane]      = a0 * inv;
        optr[lane + 32] = a1 * inv;
    }
}

// ---------------------------------------------------------------------------
extern "C" void kernel_launch(void* const* d_in, const int* in_sizes, int n_in,
                              void* d_out, int out_size)
{
    const float* x    = (const float*)d_in[0];
    const float* Wqkv = (const float*)d_in[1];
    const float* bqkv = (const float*)d_in[2];
    const float* Wout = (const float*)d_in[3];
    const float* bout = (const float*)d_in[4];
    float* out = (float*)d_out;

    float *qkv_ptr, *attn_ptr;
    cudaGetSymbolAddress((void**)&qkv_ptr, g_qkv);
    cudaGetSymbolAddress((void**)&attn_ptr, g_attn);

    // 1) QKV projection: [8192,1024] x [3072,1024]^T
    gemm_nt_bias<<<dim3((3 * D_MODEL) / BN, M_TOT / BM), 256>>>(
        x, Wqkv, bqkv, qkv_ptr, M_TOT, 3 * D_MODEL, D_MODEL);

    // 2) Local attention
    attn_local<<<dim3(T_SEQ / QT, NH, BATCH), 256>>>(qkv_ptr, attn_ptr);

    // 3) Output projection: [8192,1024] x [1024,1024]^T
    gemm_nt_bias<<<dim3(D_MODEL / BN, M_TOT / BM), 256>>>(
        attn_ptr, Wout, bout, out, M_TOT, D_MODEL, D_MODEL);
}

// round 3
// speedup vs baseline: 1.9037x; 1.9037x over previous
#include <cuda_runtime.h>
#include <cuda_bf16.h>
#include <cstdint>

#define T_SEQ 2048
#define D_MODEL 1024
#define NH 16
#define HD 64
#define BATCH 4
#define M_TOT (BATCH * T_SEQ)       // 8192
#define N_QKV (3 * D_MODEL)         // 3072

// ---------------- scratch (__device__ globals: allocation-free) -------------
__device__ float g_qkv[(size_t)M_TOT * N_QKV];          // 96 MB
__device__ __nv_bfloat16 g_xhi[(size_t)M_TOT * D_MODEL];
__device__ __nv_bfloat16 g_xlo[(size_t)M_TOT * D_MODEL];
__device__ __nv_bfloat16 g_wqhi[(size_t)N_QKV * D_MODEL];
__device__ __nv_bfloat16 g_wqlo[(size_t)N_QKV * D_MODEL];
__device__ __nv_bfloat16 g_wohi[(size_t)D_MODEL * D_MODEL];
__device__ __nv_bfloat16 g_wolo[(size_t)D_MODEL * D_MODEL];
__device__ __nv_bfloat16 g_ahi[(size_t)M_TOT * D_MODEL];
__device__ __nv_bfloat16 g_alo[(size_t)M_TOT * D_MODEL];

// ---------------- helpers ---------------------------------------------------
__device__ __forceinline__ uint32_t smem_u32(const void* p) {
    uint32_t a;
    asm("{ .reg .u64 t; cvta.to.shared.u64 t, %1; cvt.u32.u64 %0, t; }"
        : "=r"(a) : "l"(p));
    return a;
}

__device__ __forceinline__ void cp_async16(uint32_t smem_dst, const void* gmem_src) {
    asm volatile("cp.async.cg.shared.global [%0], [%1], 16;"
                 :: "r"(smem_dst), "l"(gmem_src) : "memory");
}
__device__ __forceinline__ void cp_commit() {
    asm volatile("cp.async.commit_group;" ::: "memory");
}
__device__ __forceinline__ void cp_wait1() {
    asm volatile("cp.async.wait_group 1;" ::: "memory");
}

__device__ __forceinline__ void ldsm_x4(uint32_t addr, uint32_t& r0, uint32_t& r1,
                                        uint32_t& r2, uint32_t& r3) {
    asm volatile("ldmatrix.sync.aligned.m8n8.x4.shared.b16 {%0,%1,%2,%3}, [%4];"
                 : "=r"(r0), "=r"(r1), "=r"(r2), "=r"(r3) : "r"(addr));
}

__device__ __forceinline__ void mma_bf16(float* d, const uint32_t* a, const uint32_t* b) {
    asm volatile(
        "mma.sync.aligned.m16n8k16.row.col.f32.bf16.bf16.f32 "
        "{%0,%1,%2,%3}, {%4,%5,%6,%7}, {%8,%9}, {%0,%1,%2,%3};"
        : "+f"(d[0]), "+f"(d[1]), "+f"(d[2]), "+f"(d[3])
        : "r"(a[0]), "r"(a[1]), "r"(a[2]), "r"(a[3]), "r"(b[0]), "r"(b[1]));
}

// ---------------- split fp32 -> bf16 hi/lo ----------------------------------
__global__ __launch_bounds__(256) void split_kernel(
    const float* __restrict__ in, __nv_bfloat16* __restrict__ hi,
    __nv_bfloat16* __restrict__ lo, int n4)
{
    int i = blockIdx.x * blockDim.x + threadIdx.x;
    if (i >= n4) return;
    float4 v = ((const float4*)in)[i];
    float f[4] = {v.x, v.y, v.z, v.w};
    __nv_bfloat16 h[4], l[4];
    #pragma unroll
    for (int j = 0; j < 4; j++) {
        h[j] = __float2bfloat16(f[j]);
        l[j] = __float2bfloat16(f[j] - __bfloat162float(h[j]));
    }
    __nv_bfloat162 h01, h23, l01, l23;
    h01.x = h[0]; h01.y = h[1]; h23.x = h[2]; h23.y = h[3];
    l01.x = l[0]; l01.y = l[1]; l23.x = l[2]; l23.y = l[3];
    uint2 hp, lp;
    hp.x = *(uint32_t*)&h01; hp.y = *(uint32_t*)&h23;
    lp.x = *(uint32_t*)&l01; lp.y = *(uint32_t*)&l23;
    *(uint2*)(hi + 4 * (size_t)i) = hp;
    *(uint2*)(lo + 4 * (size_t)i) = lp;
}

// ---------------- HMMA GEMM: C[M,N] = (Ahi+Alo)(Bhi+Blo)^T + bias -----------
// K = 1024 fixed, K-major operands. CTA 128x128, 8 warps (4m x 2n), warp
// tile 32x64. K-chunk 32, cp.async double-buffered. smem rows padded to
// 80 bytes (mult of 16 -> ldmatrix-legal; 20i mod 32 -> conflict-free).
#define KC 32
#define LDROW 80                     // bytes per smem row (32 bf16 + 8 pad)
#define TILE_B (128 * LDROW)         // 10240 B per operand tile
#define STAGE_B (4 * TILE_B)         // Ahi,Alo,Bhi,Blo
#define SMEM_BYTES (2 * STAGE_B)     // 81920
#define NCHUNK (1024 / KC)           // 32

__global__ __launch_bounds__(256) void gemm_hmma(
    const __nv_bfloat16* __restrict__ Ahi, const __nv_bfloat16* __restrict__ Alo,
    const __nv_bfloat16* __restrict__ Bhi, const __nv_bfloat16* __restrict__ Blo,
    const float* __restrict__ bias, float* __restrict__ C, int N)
{
    extern __shared__ char smem[];
    const int tid  = threadIdx.x;
    const int wid  = tid >> 5, lane = tid & 31;
    const int wm   = wid >> 1, wn = wid & 1;       // 4 x 2 warps
    const int bn   = blockIdx.x * 128, bm = blockIdx.y * 128;
    const uint32_t sbase = smem_u32(smem);

    const char* gsrc[4];
    gsrc[0] = (const char*)Ahi + (size_t)bm * 2048;
    gsrc[1] = (const char*)Alo + (size_t)bm * 2048;
    gsrc[2] = (const char*)Bhi + (size_t)bn * 2048;
    gsrc[3] = (const char*)Blo + (size_t)bn * 2048;

    // per-thread cp.async coords (8 ops / stage): idx -> (tile, row, 16B col)
    int ld_which[8], ld_row[8], ld_c16[8];
    #pragma unroll
    for (int i = 0; i < 8; i++) {
        int idx = tid + i * 256;
        ld_which[i] = idx >> 9;
        ld_row[i]   = (idx & 511) >> 2;
        ld_c16[i]   = idx & 3;
    }

    auto load_stage = [&](int chunk, int buf) {
        const size_t k0b = (size_t)chunk * (KC * 2);
        uint32_t sdst = sbase + buf * STAGE_B;
        #pragma unroll
        for (int i = 0; i < 8; i++) {
            const char* g = gsrc[ld_which[i]] + (size_t)ld_row[i] * 2048 + k0b + ld_c16[i] * 16;
            uint32_t s = sdst + ld_which[i] * TILE_B + ld_row[i] * LDROW + ld_c16[i] * 16;
            cp_async16(s, g);
        }
    };

    float acc[2][8][4];
    #pragma unroll
    for (int mt = 0; mt < 2; mt++)
        #pragma unroll
        for (int nt = 0; nt < 8; nt++)
            #pragma unroll
            for (int j = 0; j < 4; j++) acc[mt][nt][j] = 0.f;

    // ldmatrix base offsets (within an operand tile)
    const uint32_t a_off = (uint32_t)(wm * 32 + (lane & 15)) * LDROW + (lane >> 4) * 16;
    const uint32_t b_off = (uint32_t)(wn * 64 + ((lane >> 4) & 1) * 8 + (lane & 7)) * LDROW
                         + ((lane >> 3) & 1) * 16;

    load_stage(0, 0);
    cp_commit();

    for (int c = 0; c < NCHUNK; c++) {
        const int buf = c & 1;
        if (c + 1 < NCHUNK) load_stage(c + 1, buf ^ 1);
        cp_commit();
        cp_wait1();
        __syncthreads();

        const uint32_t st = sbase + buf * STAGE_B;
        const uint32_t tAhi = st, tAlo = st + TILE_B;
        const uint32_t tBhi = st + 2 * TILE_B, tBlo = st + 3 * TILE_B;

        #pragma unroll
        for (int ks = 0; ks < 2; ks++) {
            const uint32_t kb = ks * 32;
            uint32_t ah[2][4], al[2][4], bh[4][4], bl[4][4];
            #pragma unroll
            for (int mt = 0; mt < 2; mt++) {
                ldsm_x4(tAhi + a_off + (uint32_t)mt * 16 * LDROW + kb,
                        ah[mt][0], ah[mt][1], ah[mt][2], ah[mt][3]);
                ldsm_x4(tAlo + a_off + (uint32_t)mt * 16 * LDROW + kb,
                        al[mt][0], al[mt][1], al[mt][2], al[mt][3]);
            }
            #pragma unroll
            for (int p = 0; p < 4; p++) {
                ldsm_x4(tBhi + b_off + (uint32_t)p * 16 * LDROW + kb,
                        bh[p][0], bh[p][1], bh[p][2], bh[p][3]);
                ldsm_x4(tBlo + b_off + (uint32_t)p * 16 * LDROW + kb,
                        bl[p][0], bl[p][1], bl[p][2], bl[p][3]);
            }
            #pragma unroll
            for (int mt = 0; mt < 2; mt++)
                #pragma unroll
                for (int nt = 0; nt < 8; nt++) {
                    const uint32_t* bhp = &bh[nt >> 1][(nt & 1) * 2];
                    const uint32_t* blp = &bl[nt >> 1][(nt & 1) * 2];
                    mma_bf16(acc[mt][nt], ah[mt], bhp);   // hh
                    mma_bf16(acc[mt][nt], ah[mt], blp);   // hl
                    mma_bf16(acc[mt][nt], al[mt], bhp);   // lh
                }
        }
        __syncthreads();
    }

    // ---------------- epilogue: stage -> coalesced stores + bias ------------
    float* stage = (float*)smem;                  // [128][132]
    #pragma unroll
    for (int mt = 0; mt < 2; mt++)
        #pragma unroll
        for (int nt = 0; nt < 8; nt++) {
            int row = wm * 32 + mt * 16 + (lane >> 2);
            int col = wn * 64 + nt * 8 + (lane & 3) * 2;
            stage[row * 132 + col]       = acc[mt][nt][0];
            stage[row * 132 + col + 1]   = acc[mt][nt][1];
            stage[(row + 8) * 132 + col]     = acc[mt][nt][2];
            stage[(row + 8) * 132 + col + 1] = acc[mt][nt][3];
        }
    __syncthreads();

    #pragma unroll
    for (int i = 0; i < 16; i++) {
        int idx = tid + i * 256;                  // 0..4095
        int row = idx >> 5;
        int c4  = (idx & 31) * 4;
        float4 bv = *(const float4*)(bias + bn + c4);
        float4 o;
        o.x = stage[row * 132 + c4 + 0] + bv.x;
        o.y = stage[row * 132 + c4 + 1] + bv.y;
        o.z = stage[row * 132 + c4 + 2] + bv.z;
        o.w = stage[row * 132 + c4 + 3] + bv.w;
        *(float4*)(C + (size_t)(bm + row) * N + bn + c4) = o;
    }
}

// ---------------- local windowed attention (writes bf16 hi/lo) --------------
#define QT 32
#define KT 96

__global__ __launch_bounds__(256) void attn_local(
    const float* __restrict__ qkv,
    __nv_bfloat16* __restrict__ ohi, __nv_bfloat16* __restrict__ olo)
{
    __shared__ float Ks[KT][HD];
    __shared__ float Vs[KT][HD];

    const int b = blockIdx.z, h = blockIdx.y;
    const int t0 = blockIdx.x * QT;
    const int kbase = t0 - 32;
    const int tid = threadIdx.x;

    #pragma unroll
    for (int i = 0; i < 6; i++) {
        int idx = tid + i * 256;
        int row = idx >> 4;
        int c   = (idx & 15) << 2;
        int tk  = kbase + row;
        if (tk >= 0 && tk < T_SEQ) {
            const float* base = qkv + ((size_t)(b * T_SEQ + tk)) * N_QKV + h * HD;
            *(float4*)&Ks[row][c] = *(const float4*)(base + D_MODEL + c);
            *(float4*)&Vs[row][c] = *(const float4*)(base + 2 * D_MODEL + c);
        }
    }
    __syncthreads();

    const int warp = tid >> 5, lane = tid & 31;
    const float scale = 0.125f;

    #pragma unroll 1
    for (int qq = 0; qq < QT / 8; qq++) {
        int qi = warp * (QT / 8) + qq;
        int t  = t0 + qi;
        const float* qptr = qkv + ((size_t)(b * T_SEQ + t)) * N_QKV + h * HD;
        float q0 = qptr[lane] * scale;
        float q1 = qptr[lane + 32] * scale;

        int jlo = qi;
        if (kbase + jlo < 0) jlo = -kbase;
        int jhi = qi + 64;
        if (kbase + jhi > T_SEQ - 1) jhi = T_SEQ - 1 - kbase;

        float m = -1e30f, l = 0.f, a0 = 0.f, a1 = 0.f;
        for (int j = jlo; j <= jhi; j++) {
            float s = q0 * Ks[j][lane] + q1 * Ks[j][lane + 32];
            s += __shfl_xor_sync(0xffffffffu, s, 16);
            s += __shfl_xor_sync(0xffffffffu, s, 8);
            s += __shfl_xor_sync(0xffffffffu, s, 4);
            s += __shfl_xor_sync(0xffffffffu, s, 2);
            s += __shfl_xor_sync(0xffffffffu, s, 1);
            float v0 = Vs[j][lane], v1 = Vs[j][lane + 32];
            if (s > m) {
                float corr = __expf(m - s);
                m = s;
                l  = l  * corr + 1.f;
                a0 = a0 * corr + v0;
                a1 = a1 * corr + v1;
            } else {
                float p = __expf(s - m);
                l  += p;
                a0 += p * v0;
                a1 += p * v1;
            }
        }
        float inv = 1.f / l;
        float o0 = a0 * inv, o1 = a1 * inv;
        size_t off = ((size_t)(b * T_SEQ + t)) * D_MODEL + h * HD;
        __nv_bfloat16 h0 = __float2bfloat16(o0);
        __nv_bfloat16 h1 = __float2bfloat16(o1);
        ohi[off + lane]      = h0;
        ohi[off + lane + 32] = h1;
        olo[off + lane]      = __float2bfloat16(o0 - __bfloat162float(h0));
        olo[off + lane + 32] = __float2bfloat16(o1 - __bfloat162float(h1));
    }
}

// ---------------------------------------------------------------------------
extern "C" void kernel_launch(void* const* d_in, const int* in_sizes, int n_in,
                              void* d_out, int out_size)
{
    const float* x    = (const float*)d_in[0];
    const float* Wqkv = (const float*)d_in[1];
    const float* bqkv = (const float*)d_in[2];
    const float* Wout = (const float*)d_in[3];
    const float* bout = (const float*)d_in[4];
    float* out = (float*)d_out;

    float* qkv_p;
    __nv_bfloat16 *xhi, *xlo, *wqhi, *wqlo, *wohi, *wolo, *ahi, *alo;
    cudaGetSymbolAddress((void**)&qkv_p, g_qkv);
    cudaGetSymbolAddress((void**)&xhi, g_xhi);
    cudaGetSymbolAddress((void**)&xlo, g_xlo);
    cudaGetSymbolAddress((void**)&wqhi, g_wqhi);
    cudaGetSymbolAddress((void**)&wqlo, g_wqlo);
    cudaGetSymbolAddress((void**)&wohi, g_wohi);
    cudaGetSymbolAddress((void**)&wolo, g_wolo);
    cudaGetSymbolAddress((void**)&ahi, g_ahi);
    cudaGetSymbolAddress((void**)&alo, g_alo);

    cudaFuncSetAttribute(gemm_hmma, cudaFuncAttributeMaxDynamicSharedMemorySize, SMEM_BYTES);

    {   // split inputs to bf16 hi/lo
        int n4 = (M_TOT * D_MODEL) / 4;
        split_kernel<<<(n4 + 255) / 256, 256>>>(x, xhi, xlo, n4);
    }
    {
        int n4 = (N_QKV * D_MODEL) / 4;
        split_kernel<<<(n4 + 255) / 256, 256>>>(Wqkv, wqhi, wqlo, n4);
    }
    {
        int n4 = (D_MODEL * D_MODEL) / 4;
        split_kernel<<<(n4 + 255) / 256, 256>>>(Wout, wohi, wolo, n4);
    }

    // 1) QKV projection (HMMA)
    gemm_hmma<<<dim3(N_QKV / 128, M_TOT / 128), 256, SMEM_BYTES>>>(
        xhi, xlo, wqhi, wqlo, bqkv, qkv_p, N_QKV);

    // 2) local attention (fp32), writes bf16 hi/lo directly
    attn_local<<<dim3(T_SEQ / QT, NH, BATCH), 256>>>(qkv_p, ahi, alo);

    // 3) output projection (HMMA)
    gemm_hmma<<<dim3(D_MODEL / 128, M_TOT / 128), 256, SMEM_BYTES>>>(
        ahi, alo, wohi, wolo, bout, out, D_MODEL);
}

// round 4
// speedup vs baseline: 3.0225x; 1.5877x over previous
#include <cuda_runtime.h>
#include <cuda_fp16.h>
#include <cstdint>

#define T_SEQ 2048
#define D_MODEL 1024
#define NH 16
#define HD 64
#define BATCH 4
#define M_TOT (BATCH * T_SEQ)       // 8192
#define N_QKV (3 * D_MODEL)         // 3072

// ---------------- scratch (__device__ globals: allocation-free) -------------
__device__ float g_qkv[(size_t)M_TOT * N_QKV];          // 96 MB
__device__ __half g_xhi[(size_t)M_TOT * D_MODEL];
__device__ __half g_xlo[(size_t)M_TOT * D_MODEL];
__device__ __half g_wq[(size_t)N_QKV * D_MODEL];
__device__ __half g_wo[(size_t)D_MODEL * D_MODEL];
__device__ __half g_ahi[(size_t)M_TOT * D_MODEL];
__device__ __half g_alo[(size_t)M_TOT * D_MODEL];

// ---------------- helpers ---------------------------------------------------
__device__ __forceinline__ uint32_t smem_u32(const void* p) {
    uint32_t a;
    asm("{ .reg .u64 t; cvta.to.shared.u64 t, %1; cvt.u32.u64 %0, t; }"
        : "=r"(a) : "l"(p));
    return a;
}
__device__ __forceinline__ void cp_async16(uint32_t smem_dst, const void* gmem_src) {
    asm volatile("cp.async.cg.shared.global [%0], [%1], 16;"
                 :: "r"(smem_dst), "l"(gmem_src) : "memory");
}
__device__ __forceinline__ void cp_commit() {
    asm volatile("cp.async.commit_group;" ::: "memory");
}
__device__ __forceinline__ void cp_wait1() {
    asm volatile("cp.async.wait_group 1;" ::: "memory");
}
__device__ __forceinline__ void ldsm_x4(uint32_t addr, uint32_t& r0, uint32_t& r1,
                                        uint32_t& r2, uint32_t& r3) {
    asm volatile("ldmatrix.sync.aligned.m8n8.x4.shared.b16 {%0,%1,%2,%3}, [%4];"
                 : "=r"(r0), "=r"(r1), "=r"(r2), "=r"(r3) : "r"(addr));
}
__device__ __forceinline__ void mma_f16(float* d, const uint32_t* a, const uint32_t* b) {
    asm volatile(
        "mma.sync.aligned.m16n8k16.row.col.f32.f16.f16.f32 "
        "{%0,%1,%2,%3}, {%4,%5,%6,%7}, {%8,%9}, {%0,%1,%2,%3};"
        : "+f"(d[0]), "+f"(d[1]), "+f"(d[2]), "+f"(d[3])
        : "r"(a[0]), "r"(a[1]), "r"(a[2]), "r"(a[3]), "r"(b[0]), "r"(b[1]));
}

// ---------------- converts ---------------------------------------------------
__global__ __launch_bounds__(256) void split_f16(
    const float* __restrict__ in, __half* __restrict__ hi,
    __half* __restrict__ lo, int n4)
{
    int i = blockIdx.x * blockDim.x + threadIdx.x;
    if (i >= n4) return;
    float4 v = ((const float4*)in)[i];
    float f[4] = {v.x, v.y, v.z, v.w};
    __half h[4], l[4];
    #pragma unroll
    for (int j = 0; j < 4; j++) {
        h[j] = __float2half_rn(f[j]);
        l[j] = __float2half_rn(f[j] - __half2float(h[j]));
    }
    *(uint2*)(hi + 4 * (size_t)i) = *(uint2*)h;
    *(uint2*)(lo + 4 * (size_t)i) = *(uint2*)l;
}

__global__ __launch_bounds__(256) void conv_f16(
    const float* __restrict__ in, __half* __restrict__ out, int n4)
{
    int i = blockIdx.x * blockDim.x + threadIdx.x;
    if (i >= n4) return;
    float4 v = ((const float4*)in)[i];
    __half h[4] = {__float2half_rn(v.x), __float2half_rn(v.y),
                   __float2half_rn(v.z), __float2half_rn(v.w)};
    *(uint2*)(out + 4 * (size_t)i) = *(uint2*)h;
}

// ---------------- HMMA GEMM: C = (Ahi+Alo) @ B^T + bias ---------------------
// fp16 operands, fp32 accum. K=1024, K-major. CTA 128x128, 8 warps (4m x 2n),
// warp tile 32x64, K-chunk 32, cp.async double-buffered. 80-byte smem rows.
#define KC 32
#define LDROW 80
#define TILE_B (128 * LDROW)         // 10240
#define STAGE_B (3 * TILE_B)         // Ahi, Alo, B = 30720
#define SMEM_BYTES 67584             // max(2*STAGE_B=61440, epilogue 128*132*4)
#define NCHUNK (1024 / KC)

__global__ __launch_bounds__(256) void gemm_hmma(
    const __half* __restrict__ Ahi, const __half* __restrict__ Alo,
    const __half* __restrict__ Bw,
    const float* __restrict__ bias, float* __restrict__ C, int N)
{
    extern __shared__ char smem[];
    const int tid  = threadIdx.x;
    const int wid  = tid >> 5, lane = tid & 31;
    const int wm   = wid >> 1, wn = wid & 1;
    const int bn   = blockIdx.x * 128, bm = blockIdx.y * 128;
    const uint32_t sbase = smem_u32(smem);

    const char* gsrc[3];
    gsrc[0] = (const char*)Ahi + (size_t)bm * 2048;
    gsrc[1] = (const char*)Alo + (size_t)bm * 2048;
    gsrc[2] = (const char*)Bw  + (size_t)bn * 2048;

    int ld_which[6], ld_row[6], ld_c16[6];
    #pragma unroll
    for (int i = 0; i < 6; i++) {
        int idx = tid + i * 256;          // 0..1535
        ld_which[i] = idx >> 9;
        ld_row[i]   = (idx & 511) >> 2;
        ld_c16[i]   = idx & 3;
    }

    auto load_stage = [&](int chunk, int buf) {
        const size_t k0b = (size_t)chunk * (KC * 2);
        uint32_t sdst = sbase + buf * STAGE_B;
        #pragma unroll
        for (int i = 0; i < 6; i++) {
            const char* g = gsrc[ld_which[i]] + (size_t)ld_row[i] * 2048 + k0b + ld_c16[i] * 16;
            uint32_t s = sdst + ld_which[i] * TILE_B + ld_row[i] * LDROW + ld_c16[i] * 16;
            cp_async16(s, g);
        }
    };

    float acc[2][8][4];
    #pragma unroll
    for (int mt = 0; mt < 2; mt++)
        #pragma unroll
        for (int nt = 0; nt < 8; nt++)
            #pragma unroll
            for (int j = 0; j < 4; j++) acc[mt][nt][j] = 0.f;

    const uint32_t a_off = (uint32_t)(wm * 32 + (lane & 15)) * LDROW + (lane >> 4) * 16;
    const uint32_t b_off = (uint32_t)(wn * 64 + ((lane >> 4) & 1) * 8 + (lane & 7)) * LDROW
                         + ((lane >> 3) & 1) * 16;

    load_stage(0, 0);
    cp_commit();

    for (int c = 0; c < NCHUNK; c++) {
        const int buf = c & 1;
        if (c + 1 < NCHUNK) load_stage(c + 1, buf ^ 1);
        cp_commit();
        cp_wait1();
        __syncthreads();

        const uint32_t st = sbase + buf * STAGE_B;
        const uint32_t tAhi = st, tAlo = st + TILE_B, tB = st + 2 * TILE_B;

        #pragma unroll
        for (int ks = 0; ks < 2; ks++) {
            const uint32_t kb = ks * 32;
            uint32_t ah[2][4], al[2][4], bb[4][4];
            #pragma unroll
            for (int mt = 0; mt < 2; mt++) {
                ldsm_x4(tAhi + a_off + (uint32_t)mt * 16 * LDROW + kb,
                        ah[mt][0], ah[mt][1], ah[mt][2], ah[mt][3]);
                ldsm_x4(tAlo + a_off + (uint32_t)mt * 16 * LDROW + kb,
                        al[mt][0], al[mt][1], al[mt][2], al[mt][3]);
            }
            #pragma unroll
            for (int p = 0; p < 4; p++)
                ldsm_x4(tB + b_off + (uint32_t)p * 16 * LDROW + kb,
                        bb[p][0], bb[p][1], bb[p][2], bb[p][3]);
            #pragma unroll
            for (int mt = 0; mt < 2; mt++)
                #pragma unroll
                for (int nt = 0; nt < 8; nt++) {
                    const uint32_t* bp = &bb[nt >> 1][(nt & 1) * 2];
                    mma_f16(acc[mt][nt], ah[mt], bp);
                    mma_f16(acc[mt][nt], al[mt], bp);
                }
        }
        __syncthreads();
    }

    // epilogue: stage -> coalesced float4 stores + bias
    float* stage = (float*)smem;                  // [128][132]
    #pragma unroll
    for (int mt = 0; mt < 2; mt++)
        #pragma unroll
        for (int nt = 0; nt < 8; nt++) {
            int row = wm * 32 + mt * 16 + (lane >> 2);
            int col = wn * 64 + nt * 8 + (lane & 3) * 2;
            stage[row * 132 + col]           = acc[mt][nt][0];
            stage[row * 132 + col + 1]       = acc[mt][nt][1];
            stage[(row + 8) * 132 + col]     = acc[mt][nt][2];
            stage[(row + 8) * 132 + col + 1] = acc[mt][nt][3];
        }
    __syncthreads();

    #pragma unroll
    for (int i = 0; i < 16; i++) {
        int idx = tid + i * 256;
        int row = idx >> 5;
        int c4  = (idx & 31) * 4;
        float4 bv = *(const float4*)(bias + bn + c4);
        float4 o;
        o.x = stage[row * 132 + c4 + 0] + bv.x;
        o.y = stage[row * 132 + c4 + 1] + bv.y;
        o.z = stage[row * 132 + c4 + 2] + bv.z;
        o.w = stage[row * 132 + c4 + 3] + bv.w;
        *(float4*)(C + (size_t)(bm + row) * N + bn + c4) = o;
    }
}

// ---------------- local windowed attention v2 --------------------------------
// Phase A: keys-in-lanes (each lane: 2 full dots + 1 cooperative dot),
// exp distributed across lanes. Phase B: dims-in-lanes P.V accumulation.
#define QT 32
#define KT 96
#define KP 68                         // padded row stride (floats)
#define ATTN_SMEM ((2 * KT * KP + QT * KP + 8 * 80) * 4)

__global__ __launch_bounds__(256) void attn_local(
    const float* __restrict__ qkv,
    __half* __restrict__ ohi, __half* __restrict__ olo)
{
    extern __shared__ float sm[];
    float* Ks = sm;                   // [96][68]
    float* Vs = sm + KT * KP;         // [96][68]
    float* Qs = sm + 2 * KT * KP;     // [32][68] (pre-scaled)
    float* Ps = sm + 2 * KT * KP + QT * KP;   // [8][80]

    const int b = blockIdx.z, h = blockIdx.y;
    const int t0 = blockIdx.x * QT;
    const int kbase = t0 - 32;
    const int tid = threadIdx.x;

    // stage K/V (zero-fill out-of-range rows)
    #pragma unroll
    for (int i = 0; i < 6; i++) {
        int idx = tid + i * 256;          // < 1536
        int row = idx >> 4;
        int c   = (idx & 15) << 2;
        int tk  = kbase + row;
        float4 kv = {0.f, 0.f, 0.f, 0.f}, vv = {0.f, 0.f, 0.f, 0.f};
        if (tk >= 0 && tk < T_SEQ) {
            const float* base = qkv + ((size_t)(b * T_SEQ + tk)) * N_QKV + h * HD;
            kv = *(const float4*)(base + D_MODEL + c);
            vv = *(const float4*)(base + 2 * D_MODEL + c);
        }
        *(float4*)&Ks[row * KP + c] = kv;
        *(float4*)&Vs[row * KP + c] = vv;
    }
    // stage Q, pre-scaled by 1/sqrt(64)
    #pragma unroll
    for (int i = 0; i < 2; i++) {
        int idx = tid + i * 256;          // < 512
        int row = idx >> 4;
        int c   = (idx & 15) << 2;
        float4 qv = *(const float4*)(qkv + ((size_t)(b * T_SEQ + t0 + row)) * N_QKV + h * HD + c);
        qv.x *= 0.125f; qv.y *= 0.125f; qv.z *= 0.125f; qv.w *= 0.125f;
        *(float4*)&Qs[row * KP + c] = qv;
    }
    __syncthreads();

    const int warp = tid >> 5, lane = tid & 31;

    #pragma unroll 1
    for (int qq = 0; qq < 4; qq++) {
        const int qi = warp * 4 + qq;
        const int t  = t0 + qi;

        // ---- phase A: scores (keys in lanes) ----
        // lane handles key offsets: lane (rows qi+lane), 32+lane (rows qi+32+lane)
        const bool v0 = (t - 32 + lane) >= 0;          // key t-32+lane
        const bool v1 = (t + lane) < T_SEQ;            // key t+lane
        float d0 = 0.f, d1 = 0.f;
        const float4* q4  = (const float4*)&Qs[qi * KP];
        const float4* k04 = (const float4*)&Ks[(qi + lane) * KP];
        const float4* k14 = (const float4*)&Ks[(qi + 32 + lane) * KP];
        #pragma unroll
        for (int c = 0; c < 16; c++) {
            float4 qv = q4[c];
            float4 ka = k04[c];
            float4 kb = k14[c];
            d0 = fmaf(qv.x, ka.x, d0); d0 = fmaf(qv.y, ka.y, d0);
            d0 = fmaf(qv.z, ka.z, d0); d0 = fmaf(qv.w, ka.w, d0);
            d1 = fmaf(qv.x, kb.x, d1); d1 = fmaf(qv.y, kb.y, d1);
            d1 = fmaf(qv.z, kb.z, d1); d1 = fmaf(qv.w, kb.w, d1);
        }
        float s0 = v0 ? d0 : -1e30f;
        float s1 = v1 ? d1 : -1e30f;

        // 65th key (offset 64 -> key t+32, row qi+64): cooperative dot
        float part = Qs[qi * KP + lane]      * Ks[(qi + 64) * KP + lane]
                   + Qs[qi * KP + lane + 32] * Ks[(qi + 64) * KP + lane + 32];
        part += __shfl_xor_sync(0xffffffffu, part, 16);
        part += __shfl_xor_sync(0xffffffffu, part, 8);
        part += __shfl_xor_sync(0xffffffffu, part, 4);
        part += __shfl_xor_sync(0xffffffffu, part, 2);
        part += __shfl_xor_sync(0xffffffffu, part, 1);
        const bool v2 = (t + 32) < T_SEQ;
        float s2 = (lane == 0 && v2) ? part : -1e30f;

        // ---- softmax ----
        float m = fmaxf(fmaxf(s0, s1), s2);
        m = fmaxf(m, __shfl_xor_sync(0xffffffffu, m, 16));
        m = fmaxf(m, __shfl_xor_sync(0xffffffffu, m, 8));
        m = fmaxf(m, __shfl_xor_sync(0xffffffffu, m, 4));
        m = fmaxf(m, __shfl_xor_sync(0xffffffffu, m, 2));
        m = fmaxf(m, __shfl_xor_sync(0xffffffffu, m, 1));
        float p0 = __expf(s0 - m);
        float p1 = __expf(s1 - m);
        float p2 = __expf(s2 - m);
        float l = p0 + p1 + p2;
        l += __shfl_xor_sync(0xffffffffu, l, 16);
        l += __shfl_xor_sync(0xffffffffu, l, 8);
        l += __shfl_xor_sync(0xffffffffu, l, 4);
        l += __shfl_xor_sync(0xffffffffu, l, 2);
        l += __shfl_xor_sync(0xffffffffu, l, 1);
        float inv = 1.f / l;

        float* pw = &Ps[warp * 80];
        pw[lane]      = p0 * inv;
        pw[lane + 32] = p1 * inv;
        if (lane == 0) pw[64] = p2 * inv;
        __syncwarp();

        // ---- phase B: out = P.V (dims in lanes) ----
        float a0 = 0.f, a1 = 0.f;
        const float* vb = &Vs[qi * KP];
        #pragma unroll 5
        for (int j = 0; j < 65; j++) {
            float p = pw[j];
            a0 = fmaf(p, vb[j * KP + lane],      a0);
            a1 = fmaf(p, vb[j * KP + lane + 32], a1);
        }

        size_t off = ((size_t)(b * T_SEQ + t)) * D_MODEL + h * HD;
        __half h0 = __float2half_rn(a0);
        __half h1 = __float2half_rn(a1);
        ohi[off + lane]      = h0;
        ohi[off + lane + 32] = h1;
        olo[off + lane]      = __float2half_rn(a0 - __half2float(h0));
        olo[off + lane + 32] = __float2half_rn(a1 - __half2float(h1));
        __syncwarp();   // Ps reused next qq
    }
}

// ---------------------------------------------------------------------------
extern "C" void kernel_launch(void* const* d_in, const int* in_sizes, int n_in,
                              void* d_out, int out_size)
{
    const float* x    = (const float*)d_in[0];
    const float* Wqkv = (const float*)d_in[1];
    const float* bqkv = (const float*)d_in[2];
    const float* Wout = (const float*)d_in[3];
    const float* bout = (const float*)d_in[4];
    float* out = (float*)d_out;

    float* qkv_p;
    __half *xhi, *xlo, *wq, *wo, *ahi, *alo;
    cudaGetSymbolAddress((void**)&qkv_p, g_qkv);
    cudaGetSymbolAddress((void**)&xhi, g_xhi);
    cudaGetSymbolAddress((void**)&xlo, g_xlo);
    cudaGetSymbolAddress((void**)&wq, g_wq);
    cudaGetSymbolAddress((void**)&wo, g_wo);
    cudaGetSymbolAddress((void**)&ahi, g_ahi);
    cudaGetSymbolAddress((void**)&alo, g_alo);

    cudaFuncSetAttribute(gemm_hmma, cudaFuncAttributeMaxDynamicSharedMemorySize, SMEM_BYTES);
    cudaFuncSetAttribute(attn_local, cudaFuncAttributeMaxDynamicSharedMemorySize, ATTN_SMEM);

    {   // x -> fp16 hi/lo
        int n4 = (M_TOT * D_MODEL) / 4;
        split_f16<<<(n4 + 255) / 256, 256>>>(x, xhi, xlo, n4);
    }
    {   // weights -> fp16
        int n4 = (N_QKV * D_MODEL) / 4;
        conv_f16<<<(n4 + 255) / 256, 256>>>(Wqkv, wq, n4);
    }
    {
        int n4 = (D_MODEL * D_MODEL) / 4;
        conv_f16<<<(n4 + 255) / 256, 256>>>(Wout, wo, n4);
    }

    // 1) QKV projection
    gemm_hmma<<<dim3(N_QKV / 128, M_TOT / 128), 256, SMEM_BYTES>>>(
        xhi, xlo, wq, bqkv, qkv_p, N_QKV);

    // 2) local attention (writes fp16 hi/lo)
    attn_local<<<dim3(T_SEQ / QT, NH, BATCH), 256, ATTN_SMEM>>>(qkv_p, ahi, alo);

    // 3) output projection
    gemm_hmma<<<dim3(D_MODEL / 128, M_TOT / 128), 256, SMEM_BYTES>>>(
        ahi, alo, wo, bout, out, D_MODEL);
}

// round 6
// speedup vs baseline: 4.1940x; 1.3876x over previous
#include <cuda_runtime.h>
#include <cuda_fp16.h>
#include <cstdint>

#define T_SEQ 2048
#define D_MODEL 1024
#define NH 16
#define HD 64
#define BATCH 4
#define M_TOT (BATCH * T_SEQ)       // 8192
#define N_QKV (3 * D_MODEL)         // 3072

// ---------------- scratch (__device__ globals: allocation-free) -------------
__device__ float g_qkv[(size_t)M_TOT * N_QKV];          // 96 MB
__device__ __half g_xh[(size_t)M_TOT * D_MODEL];
__device__ __half g_wq[(size_t)N_QKV * D_MODEL];
__device__ __half g_wo[(size_t)D_MODEL * D_MODEL];
__device__ __half g_ah[(size_t)M_TOT * D_MODEL];

// ---------------- helpers ---------------------------------------------------
__device__ __forceinline__ uint32_t smem_u32(const void* p) {
    uint32_t a;
    asm("{ .reg .u64 t; cvta.to.shared.u64 t, %1; cvt.u32.u64 %0, t; }"
        : "=r"(a) : "l"(p));
    return a;
}
__device__ __forceinline__ void cp_async16(uint32_t smem_dst, const void* gmem_src) {
    asm volatile("cp.async.cg.shared.global [%0], [%1], 16;"
                 :: "r"(smem_dst), "l"(gmem_src) : "memory");
}
__device__ __forceinline__ void cp_commit() {
    asm volatile("cp.async.commit_group;" ::: "memory");
}
__device__ __forceinline__ void cp_wait1() {
    asm volatile("cp.async.wait_group 1;" ::: "memory");
}
__device__ __forceinline__ void ldsm_x4(uint32_t addr, uint32_t& r0, uint32_t& r1,
                                        uint32_t& r2, uint32_t& r3) {
    asm volatile("ldmatrix.sync.aligned.m8n8.x4.shared.b16 {%0,%1,%2,%3}, [%4];"
                 : "=r"(r0), "=r"(r1), "=r"(r2), "=r"(r3) : "r"(addr));
}
__device__ __forceinline__ void mma_f16(float* d, const uint32_t* a, const uint32_t* b) {
    asm volatile(
        "mma.sync.aligned.m16n8k16.row.col.f32.f16.f16.f32 "
        "{%0,%1,%2,%3}, {%4,%5,%6,%7}, {%8,%9}, {%0,%1,%2,%3};"
        : "+f"(d[0]), "+f"(d[1]), "+f"(d[2]), "+f"(d[3])
        : "r"(a[0]), "r"(a[1]), "r"(a[2]), "r"(a[3]), "r"(b[0]), "r"(b[1]));
}

// ---------------- fp32 -> fp16 convert ---------------------------------------
__global__ __launch_bounds__(256) void conv_f16(
    const float* __restrict__ in, __half* __restrict__ out, int n4)
{
    int i = blockIdx.x * blockDim.x + threadIdx.x;
    if (i >= n4) return;
    float4 v = ((const float4*)in)[i];
    __half h[4] = {__float2half_rn(v.x), __float2half_rn(v.y),
                   __float2half_rn(v.z), __float2half_rn(v.w)};
    *(uint2*)(out + 4 * (size_t)i) = *(uint2*)h;
}

// ---------------- HMMA GEMM: C = A @ B^T + bias ------------------------------
// fp16 operands, fp32 accum. K=1024 fixed, K-major. CTA 128x128, 8 warps
// (4m x 2n), warp tile 32x64, K-chunk 32, 3-stage cp.async pipeline with
// ONE __syncthreads per chunk. 80-byte padded smem rows.
#define KC 32
#define LDROW 80
#define TILE_B (128 * LDROW)         // 10240
#define STAGE_B (2 * TILE_B)         // A, B = 20480
#define SMEM_BYTES 67584             // max(3*STAGE_B=61440, epilogue 128*132*4)
#define NCHUNK (1024 / KC)           // 32

__global__ __launch_bounds__(256) void gemm_hmma(
    const __half* __restrict__ A, const __half* __restrict__ Bw,
    const float* __restrict__ bias, float* __restrict__ C, int N)
{
    extern __shared__ char smem[];
    const int tid  = threadIdx.x;
    const int wid  = tid >> 5, lane = tid & 31;
    const int wm   = wid >> 1, wn = wid & 1;
    const int bn   = blockIdx.x * 128, bm = blockIdx.y * 128;
    const uint32_t sbase = smem_u32(smem);

    const char* gsrc[2];
    gsrc[0] = (const char*)A  + (size_t)bm * 2048;
    gsrc[1] = (const char*)Bw + (size_t)bn * 2048;

    int ld_which[4], ld_row[4], ld_c16[4];
    #pragma unroll
    for (int i = 0; i < 4; i++) {
        int idx = tid + i * 256;          // 0..1023
        ld_which[i] = idx >> 9;
        ld_row[i]   = (idx & 511) >> 2;
        ld_c16[i]   = idx & 3;
    }

    auto load_stage = [&](int chunk, int slot) {
        const size_t k0b = (size_t)chunk * (KC * 2);
        uint32_t sdst = sbase + slot * STAGE_B;
        #pragma unroll
        for (int i = 0; i < 4; i++) {
            const char* g = gsrc[ld_which[i]] + (size_t)ld_row[i] * 2048 + k0b + ld_c16[i] * 16;
            uint32_t s = sdst + ld_which[i] * TILE_B + ld_row[i] * LDROW + ld_c16[i] * 16;
            cp_async16(s, g);
        }
    };

    float acc[2][8][4];
    #pragma unroll
    for (int mt = 0; mt < 2; mt++)
        #pragma unroll
        for (int nt = 0; nt < 8; nt++)
            #pragma unroll
            for (int j = 0; j < 4; j++) acc[mt][nt][j] = 0.f;

    const uint32_t a_off = (uint32_t)(wm * 32 + (lane & 15)) * LDROW + (lane >> 4) * 16;
    const uint32_t b_off = (uint32_t)(wn * 64 + ((lane >> 4) & 1) * 8 + (lane & 7)) * LDROW
                         + ((lane >> 3) & 1) * 16;

    load_stage(0, 0); cp_commit();
    load_stage(1, 1); cp_commit();

    int slot = 0;
    for (int c = 0; c < NCHUNK; c++) {
        cp_wait1();                       // chunk c resident
        __syncthreads();                  // also protects slot being overwritten below
        if (c + 2 < NCHUNK) {
            int wslot = slot + 2; if (wslot >= 3) wslot -= 3;
            load_stage(c + 2, wslot);
        }
        cp_commit();                      // keep group accounting uniform

        const uint32_t st = sbase + slot * STAGE_B;
        const uint32_t tA = st, tB = st + TILE_B;

        #pragma unroll
        for (int ks = 0; ks < 2; ks++) {
            const uint32_t kb = ks * 32;
            uint32_t aa[2][4], bb[4][4];
            #pragma unroll
            for (int mt = 0; mt < 2; mt++)
                ldsm_x4(tA + a_off + (uint32_t)mt * 16 * LDROW + kb,
                        aa[mt][0], aa[mt][1], aa[mt][2], aa[mt][3]);
            #pragma unroll
            for (int p = 0; p < 4; p++)
                ldsm_x4(tB + b_off + (uint32_t)p * 16 * LDROW + kb,
                        bb[p][0], bb[p][1], bb[p][2], bb[p][3]);
            #pragma unroll
            for (int mt = 0; mt < 2; mt++)
                #pragma unroll
                for (int nt = 0; nt < 8; nt++)
                    mma_f16(acc[mt][nt], aa[mt], &bb[nt >> 1][(nt & 1) * 2]);
        }
        if (++slot == 3) slot = 0;
    }
    __syncthreads();                      // last compute done before smem reuse

    // epilogue: stage -> coalesced float4 stores + bias
    float* stage = (float*)smem;          // [128][132]
    #pragma unroll
    for (int mt = 0; mt < 2; mt++)
        #pragma unroll
        for (int nt = 0; nt < 8; nt++) {
            int row = wm * 32 + mt * 16 + (lane >> 2);
            int col = wn * 64 + nt * 8 + (lane & 3) * 2;
            stage[row * 132 + col]           = acc[mt][nt][0];
            stage[row * 132 + col + 1]       = acc[mt][nt][1];
            stage[(row + 8) * 132 + col]     = acc[mt][nt][2];
            stage[(row + 8) * 132 + col + 1] = acc[mt][nt][3];
        }
    __syncthreads();

    #pragma unroll
    for (int i = 0; i < 16; i++) {
        int idx = tid + i * 256;
        int row = idx >> 5;
        int c4  = (idx & 31) * 4;
        float4 bv = *(const float4*)(bias + bn + c4);
        float4 o;
        o.x = stage[row * 132 + c4 + 0] + bv.x;
        o.y = stage[row * 132 + c4 + 1] + bv.y;
        o.z = stage[row * 132 + c4 + 2] + bv.z;
        o.w = stage[row * 132 + c4 + 3] + bv.w;
        *(float4*)(C + (size_t)(bm + row) * N + bn + c4) = o;
    }
}

// ---------------- local windowed attention -----------------------------------
// Phase A: keys-in-lanes (each lane: 2 full dots + 1 cooperative dot).
// Phase B: dims-in-lanes P.V accumulation. Output: single fp16 plane.
#define QT 32
#define KT 96
#define KP 68
#define ATTN_SMEM ((2 * KT * KP + QT * KP + 8 * 80) * 4)

__global__ __launch_bounds__(256) void attn_local(
    const float* __restrict__ qkv, __half* __restrict__ outh)
{
    extern __shared__ float sm[];
    float* Ks = sm;                   // [96][68]
    float* Vs = sm + KT * KP;         // [96][68]
    float* Qs = sm + 2 * KT * KP;     // [32][68] pre-scaled
    float* Ps = sm + 2 * KT * KP + QT * KP;   // [8][80]

    const int b = blockIdx.z, h = blockIdx.y;
    const int t0 = blockIdx.x * QT;
    const int kbase = t0 - 32;
    const int tid = threadIdx.x;

    #pragma unroll
    for (int i = 0; i < 6; i++) {
        int idx = tid + i * 256;
        int row = idx >> 4;
        int c   = (idx & 15) << 2;
        int tk  = kbase + row;
        float4 kv = {0.f, 0.f, 0.f, 0.f}, vv = {0.f, 0.f, 0.f, 0.f};
        if (tk >= 0 && tk < T_SEQ) {
            const float* base = qkv + ((size_t)(b * T_SEQ + tk)) * N_QKV + h * HD;
            kv = *(const float4*)(base + D_MODEL + c);
            vv = *(const float4*)(base + 2 * D_MODEL + c);
        }
        *(float4*)&Ks[row * KP + c] = kv;
        *(float4*)&Vs[row * KP + c] = vv;
    }
    #pragma unroll
    for (int i = 0; i < 2; i++) {
        int idx = tid + i * 256;
        int row = idx >> 4;
        int c   = (idx & 15) << 2;
        float4 qv = *(const float4*)(qkv + ((size_t)(b * T_SEQ + t0 + row)) * N_QKV + h * HD + c);
        qv.x *= 0.125f; qv.y *= 0.125f; qv.z *= 0.125f; qv.w *= 0.125f;
        *(float4*)&Qs[row * KP + c] = qv;
    }
    __syncthreads();

    const int warp = tid >> 5, lane = tid & 31;

    #pragma unroll 1
    for (int qq = 0; qq < 4; qq++) {
        const int qi = warp * 4 + qq;
        const int t  = t0 + qi;

        const bool v0 = (t - 32 + lane) >= 0;
        const bool v1 = (t + lane) < T_SEQ;
        float d0 = 0.f, d1 = 0.f;
        const float4* q4  = (const float4*)&Qs[qi * KP];
        const float4* k04 = (const float4*)&Ks[(qi + lane) * KP];
        const float4* k14 = (const float4*)&Ks[(qi + 32 + lane) * KP];
        #pragma unroll
        for (int c = 0; c < 16; c++) {
            float4 qv = q4[c];
            float4 ka = k04[c];
            float4 kb = k14[c];
            d0 = fmaf(qv.x, ka.x, d0); d0 = fmaf(qv.y, ka.y, d0);
            d0 = fmaf(qv.z, ka.z, d0); d0 = fmaf(qv.w, ka.w, d0);
            d1 = fmaf(qv.x, kb.x, d1); d1 = fmaf(qv.y, kb.y, d1);
            d1 = fmaf(qv.z, kb.z, d1); d1 = fmaf(qv.w, kb.w, d1);
        }
        float s0 = v0 ? d0 : -1e30f;
        float s1 = v1 ? d1 : -1e30f;

        float part = Qs[qi * KP + lane]      * Ks[(qi + 64) * KP + lane]
                   + Qs[qi * KP + lane + 32] * Ks[(qi + 64) * KP + lane + 32];
        part += __shfl_xor_sync(0xffffffffu, part, 16);
        part += __shfl_xor_sync(0xffffffffu, part, 8);
        part += __shfl_xor_sync(0xffffffffu, part, 4);
        part += __shfl_xor_sync(0xffffffffu, part, 2);
        part += __shfl_xor_sync(0xffffffffu, part, 1);
        const bool v2 = (t + 32) < T_SEQ;
        float s2 = (lane == 0 && v2) ? part : -1e30f;

        float m = fmaxf(fmaxf(s0, s1), s2);
        m = fmaxf(m, __shfl_xor_sync(0xffffffffu, m, 16));
        m = fmaxf(m, __shfl_xor_sync(0xffffffffu, m, 8));
        m = fmaxf(m, __shfl_xor_sync(0xffffffffu, m, 4));
        m = fmaxf(m, __shfl_xor_sync(0xffffffffu, m, 2));
        m = fmaxf(m, __shfl_xor_sync(0xffffffffu, m, 1));
        float p0 = __expf(s0 - m);
        float p1 = __expf(s1 - m);
        float p2 = __expf(s2 - m);
        float l = p0 + p1 + p2;
        l += __shfl_xor_sync(0xffffffffu, l, 16);
        l += __shfl_xor_sync(0xffffffffu, l, 8);
        l += __shfl_xor_sync(0xffffffffu, l, 4);
        l += __shfl_xor_sync(0xffffffffu, l, 2);
        l += __shfl_xor_sync(0xffffffffu, l, 1);
        float inv = 1.f / l;

        float* pw = &Ps[warp * 80];
        pw[lane]      = p0 * inv;
        pw[lane + 32] = p1 * inv;
        if (lane == 0) pw[64] = p2 * inv;
        __syncwarp();

        float a0 = 0.f, a1 = 0.f;
        const float* vb = &Vs[qi * KP];
        #pragma unroll 5
        for (int j = 0; j < 65; j++) {
            float p = pw[j];
            a0 = fmaf(p, vb[j * KP + lane],      a0);
            a1 = fmaf(p, vb[j * KP + lane + 32], a1);
        }

        size_t off = ((size_t)(b * T_SEQ + t)) * D_MODEL + h * HD;
        outh[off + lane]      = __float2half_rn(a0);
        outh[off + lane + 32] = __float2half_rn(a1);
        __syncwarp();
    }
}

// ---------------------------------------------------------------------------
extern "C" void kernel_launch(void* const* d_in, const int* in_sizes, int n_in,
                              void* d_out, int out_size)
{
    const float* x    = (const float*)d_in[0];
    const float* Wqkv = (const float*)d_in[1];
    const float* bqkv = (const float*)d_in[2];
    const float* Wout = (const float*)d_in[3];
    const float* bout = (const float*)d_in[4];
    float* out = (float*)d_out;

    float* qkv_p;
    __half *xh, *wq, *wo, *ah;
    cudaGetSymbolAddress((void**)&qkv_p, g_qkv);
    cudaGetSymbolAddress((void**)&xh, g_xh);
    cudaGetSymbolAddress((void**)&wq, g_wq);
    cudaGetSymbolAddress((void**)&wo, g_wo);
    cudaGetSymbolAddress((void**)&ah, g_ah);

    cudaFuncSetAttribute(gemm_hmma, cudaFuncAttributeMaxDynamicSharedMemorySize, SMEM_BYTES);
    cudaFuncSetAttribute(attn_local, cudaFuncAttributeMaxDynamicSharedMemorySize, ATTN_SMEM);

    {   int n4 = (M_TOT * D_MODEL) / 4;
        conv_f16<<<(n4 + 255) / 256, 256>>>(x, xh, n4); }
    {   int n4 = (N_QKV * D_MODEL) / 4;
        conv_f16<<<(n4 + 255) / 256, 256>>>(Wqkv, wq, n4); }
    {   int n4 = (D_MODEL * D_MODEL) / 4;
        conv_f16<<<(n4 + 255) / 256, 256>>>(Wout, wo, n4); }

    // 1) QKV projection
    gemm_hmma<<<dim3(N_QKV / 128, M_TOT / 128), 256, SMEM_BYTES>>>(
        xh, wq, bqkv, qkv_p, N_QKV);

    // 2) local attention (fp16 output)
    attn_local<<<dim3(T_SEQ / QT, NH, BATCH), 256, ATTN_SMEM>>>(qkv_p, ah);

    // 3) output projection
    gemm_hmma<<<dim3(D_MODEL / 128, M_TOT / 128), 256, SMEM_BYTES>>>(
        ah, wo, bout, out, D_MODEL);
}

// round 7
// speedup vs baseline: 4.4013x; 1.0494x over previous
#include <cuda_runtime.h>
#include <cuda_fp16.h>
#include <cstdint>

#define T_SEQ 2048
#define D_MODEL 1024
#define NH 16
#define HD 64
#define BATCH 4
#define M_TOT (BATCH * T_SEQ)       // 8192
#define N_QKV (3 * D_MODEL)         // 3072

// ---------------- scratch (__device__ globals: allocation-free) -------------
__device__ float g_qkv[(size_t)M_TOT * N_QKV];          // 96 MB
__device__ __half g_xh[(size_t)M_TOT * D_MODEL];
__device__ __half g_wq[(size_t)N_QKV * D_MODEL];
__device__ __half g_wo[(size_t)D_MODEL * D_MODEL];
__device__ __half g_ah[(size_t)M_TOT * D_MODEL];

// ---------------- helpers ---------------------------------------------------
__device__ __forceinline__ uint32_t smem_u32(const void* p) {
    uint32_t a;
    asm("{ .reg .u64 t; cvta.to.shared.u64 t, %1; cvt.u32.u64 %0, t; }"
        : "=r"(a) : "l"(p));
    return a;
}
__device__ __forceinline__ void cp_async16(uint32_t smem_dst, const void* gmem_src) {
    asm volatile("cp.async.cg.shared.global [%0], [%1], 16;"
                 :: "r"(smem_dst), "l"(gmem_src) : "memory");
}
__device__ __forceinline__ void cp_commit() {
    asm volatile("cp.async.commit_group;" ::: "memory");
}
__device__ __forceinline__ void cp_wait1() {
    asm volatile("cp.async.wait_group 1;" ::: "memory");
}
__device__ __forceinline__ void ldsm_x4(uint32_t addr, uint32_t& r0, uint32_t& r1,
                                        uint32_t& r2, uint32_t& r3) {
    asm volatile("ldmatrix.sync.aligned.m8n8.x4.shared.b16 {%0,%1,%2,%3}, [%4];"
                 : "=r"(r0), "=r"(r1), "=r"(r2), "=r"(r3) : "r"(addr));
}
__device__ __forceinline__ void mma_f16(float* d, const uint32_t* a, const uint32_t* b) {
    asm volatile(
        "mma.sync.aligned.m16n8k16.row.col.f32.f16.f16.f32 "
        "{%0,%1,%2,%3}, {%4,%5,%6,%7}, {%8,%9}, {%0,%1,%2,%3};"
        : "+f"(d[0]), "+f"(d[1]), "+f"(d[2]), "+f"(d[3])
        : "r"(a[0]), "r"(a[1]), "r"(a[2]), "r"(a[3]), "r"(b[0]), "r"(b[1]));
}

// ---------------- fp32 -> fp16 convert ---------------------------------------
__global__ __launch_bounds__(256) void conv_f16(
    const float* __restrict__ in, __half* __restrict__ out, int n4)
{
    int i = blockIdx.x * blockDim.x + threadIdx.x;
    if (i >= n4) return;
    float4 v = ((const float4*)in)[i];
    __half h[4] = {__float2half_rn(v.x), __float2half_rn(v.y),
                   __float2half_rn(v.z), __float2half_rn(v.w)};
    *(uint2*)(out + 4 * (size_t)i) = *(uint2*)h;
}

// ---------------- HMMA GEMM: C = A @ B^T + bias ------------------------------
// fp16 operands, fp32 accum. K=1024 fixed, K-major. CTA 128x128, 8 warps
// (4m x 2n), warp tile 32x64. K-chunk 64, 3-stage cp.async pipeline, ONE
// __syncthreads per chunk (16 chunks). 144-byte padded smem rows
// (144/4 = 36 ≡ 4 mod 32 -> conflict-free ldmatrix phases).
#define KC 64
#define LDROW 144
#define TILE_B (128 * LDROW)         // 18432
#define STAGE_B (2 * TILE_B)         // A, B = 36864
#define SMEM_BYTES (3 * STAGE_B)     // 110592 (epilogue needs 67584 < this)
#define NCHUNK (1024 / KC)           // 16

__global__ __launch_bounds__(256) void gemm_hmma(
    const __half* __restrict__ A, const __half* __restrict__ Bw,
    const float* __restrict__ bias, float* __restrict__ C, int N)
{
    extern __shared__ char smem[];
    const int tid  = threadIdx.x;
    const int wid  = tid >> 5, lane = tid & 31;
    const int wm   = wid >> 1, wn = wid & 1;
    const int bn   = blockIdx.x * 128, bm = blockIdx.y * 128;
    const uint32_t sbase = smem_u32(smem);

    const char* gsrc[2];
    gsrc[0] = (const char*)A  + (size_t)bm * 2048;
    gsrc[1] = (const char*)Bw + (size_t)bn * 2048;

    // 2048 cp.async16 per stage -> 8 per thread
    int ld_which[8], ld_row[8], ld_c16[8];
    #pragma unroll
    for (int i = 0; i < 8; i++) {
        int idx = tid + i * 256;          // 0..2047
        ld_which[i] = idx >> 10;
        ld_row[i]   = (idx >> 3) & 127;
        ld_c16[i]   = idx & 7;
    }

    auto load_stage = [&](int chunk, int slot) {
        const size_t k0b = (size_t)chunk * (KC * 2);
        uint32_t sdst = sbase + slot * STAGE_B;
        #pragma unroll
        for (int i = 0; i < 8; i++) {
            const char* g = gsrc[ld_which[i]] + (size_t)ld_row[i] * 2048 + k0b + ld_c16[i] * 16;
            uint32_t s = sdst + ld_which[i] * TILE_B + ld_row[i] * LDROW + ld_c16[i] * 16;
            cp_async16(s, g);
        }
    };

    float acc[2][8][4];
    #pragma unroll
    for (int mt = 0; mt < 2; mt++)
        #pragma unroll
        for (int nt = 0; nt < 8; nt++)
            #pragma unroll
            for (int j = 0; j < 4; j++) acc[mt][nt][j] = 0.f;

    const uint32_t a_off = (uint32_t)(wm * 32 + (lane & 15)) * LDROW + (lane >> 4) * 16;
    const uint32_t b_off = (uint32_t)(wn * 64 + ((lane >> 4) & 1) * 8 + (lane & 7)) * LDROW
                         + ((lane >> 3) & 1) * 16;

    load_stage(0, 0); cp_commit();
    load_stage(1, 1); cp_commit();

    for (int c = 0; c < NCHUNK; c++) {
        const int slot = c % 3;
        cp_wait1();                       // chunk c resident
        __syncthreads();                  // also: everyone done with slot (c+2)%3
        if (c + 2 < NCHUNK) load_stage(c + 2, (c + 2) % 3);
        cp_commit();                      // uniform group accounting

        const uint32_t st = sbase + slot * STAGE_B;
        const uint32_t tA = st, tB = st + TILE_B;

        #pragma unroll
        for (int ks = 0; ks < 4; ks++) {
            const uint32_t kb = ks * 32;
            uint32_t aa[2][4], bb[4][4];
            #pragma unroll
            for (int mt = 0; mt < 2; mt++)
                ldsm_x4(tA + a_off + (uint32_t)mt * 16 * LDROW + kb,
                        aa[mt][0], aa[mt][1], aa[mt][2], aa[mt][3]);
            #pragma unroll
            for (int p = 0; p < 4; p++)
                ldsm_x4(tB + b_off + (uint32_t)p * 16 * LDROW + kb,
                        bb[p][0], bb[p][1], bb[p][2], bb[p][3]);
            #pragma unroll
            for (int mt = 0; mt < 2; mt++)
                #pragma unroll
                for (int nt = 0; nt < 8; nt++)
                    mma_f16(acc[mt][nt], aa[mt], &bb[nt >> 1][(nt & 1) * 2]);
        }
    }
    __syncthreads();                      // all compute done before smem reuse

    // epilogue: stage -> coalesced float4 stores + bias
    float* stage = (float*)smem;          // [128][132]
    #pragma unroll
    for (int mt = 0; mt < 2; mt++)
        #pragma unroll
        for (int nt = 0; nt < 8; nt++) {
            int row = wm * 32 + mt * 16 + (lane >> 2);
            int col = wn * 64 + nt * 8 + (lane & 3) * 2;
            stage[row * 132 + col]           = acc[mt][nt][0];
            stage[row * 132 + col + 1]       = acc[mt][nt][1];
            stage[(row + 8) * 132 + col]     = acc[mt][nt][2];
            stage[(row + 8) * 132 + col + 1] = acc[mt][nt][3];
        }
    __syncthreads();

    #pragma unroll
    for (int i = 0; i < 16; i++) {
        int idx = tid + i * 256;
        int row = idx >> 5;
        int c4  = (idx & 31) * 4;
        float4 bv = *(const float4*)(bias + bn + c4);
        float4 o;
        o.x = stage[row * 132 + c4 + 0] + bv.x;
        o.y = stage[row * 132 + c4 + 1] + bv.y;
        o.z = stage[row * 132 + c4 + 2] + bv.z;
        o.w = stage[row * 132 + c4 + 3] + bv.w;
        *(float4*)(C + (size_t)(bm + row) * N + bn + c4) = o;
    }
}

// ---------------- local windowed attention -----------------------------------
// Phase A: keys-in-lanes scores. Phase B: dims-in-lanes P.V with V stored
// INTERLEAVED (dims d and d+32 adjacent) -> one LDS.64 per key, and P read
// 4-at-a-time via broadcast LDS.128. Rows 96..99 of V zero-filled (p=0 there).
#define QT 32
#define KT 96
#define KTV 100                       // V rows incl. zero padding for 4x unroll
#define KP 68                         // padded row stride (floats)
// floats: Ks 96*68, Vs 100*68, Qs 32*68, Ps 8*80
#define OFF_VS (KT * KP)
#define OFF_QS (OFF_VS + KTV * KP)
#define OFF_PS (OFF_QS + QT * KP)
#define ATTN_SMEM ((OFF_PS + 8 * 80) * 4)

__global__ __launch_bounds__(256) void attn_local(
    const float* __restrict__ qkv, __half* __restrict__ outh)
{
    extern __shared__ float sm[];
    float* Ks = sm;
    float* Vs = sm + OFF_VS;
    float* Qs = sm + OFF_QS;
    float* Ps = sm + OFF_PS;

    const int b = blockIdx.z, h = blockIdx.y;
    const int t0 = blockIdx.x * QT;
    const int kbase = t0 - 32;
    const int tid = threadIdx.x;

    // stage K (linear) and V (interleaved), zero-fill out-of-range
    #pragma unroll
    for (int i = 0; i < 6; i++) {
        int idx = tid + i * 256;          // < 1536
        int row = idx >> 4;
        int c   = (idx & 15) << 2;        // dim 0..60, aligned 4
        int tk  = kbase + row;
        float4 kv = {0.f, 0.f, 0.f, 0.f}, vv = {0.f, 0.f, 0.f, 0.f};
        if (tk >= 0 && tk < T_SEQ) {
            const float* base = qkv + ((size_t)(b * T_SEQ + tk)) * N_QKV + h * HD;
            kv = *(const float4*)(base + D_MODEL + c);
            vv = *(const float4*)(base + 2 * D_MODEL + c);
        }
        *(float4*)&Ks[row * KP + c] = kv;
        // interleave: dim d -> col (d<32 ? 2d : 2(d-32)+1); c..c+3 same half
        int colb = (c < 32) ? (2 * c) : (2 * (c - 32) + 1);
        Vs[row * KP + colb]     = vv.x;
        Vs[row * KP + colb + 2] = vv.y;
        Vs[row * KP + colb + 4] = vv.z;
        Vs[row * KP + colb + 6] = vv.w;
    }
    // zero V padding rows 96..99
    for (int idx = tid; idx < 4 * KP; idx += 256)
        Vs[KT * KP + idx] = 0.f;
    // stage Q, pre-scaled
    #pragma unroll
    for (int i = 0; i < 2; i++) {
        int idx = tid + i * 256;
        int row = idx >> 4;
        int c   = (idx & 15) << 2;
        float4 qv = *(const float4*)(qkv + ((size_t)(b * T_SEQ + t0 + row)) * N_QKV + h * HD + c);
        qv.x *= 0.125f; qv.y *= 0.125f; qv.z *= 0.125f; qv.w *= 0.125f;
        *(float4*)&Qs[row * KP + c] = qv;
    }
    __syncthreads();

    const int warp = tid >> 5, lane = tid & 31;

    #pragma unroll 1
    for (int qq = 0; qq < 4; qq++) {
        const int qi = warp * 4 + qq;
        const int t  = t0 + qi;

        // ---- phase A: scores (keys in lanes) ----
        const bool v0 = (t - 32 + lane) >= 0;
        const bool v1 = (t + lane) < T_SEQ;
        float d0 = 0.f, d1 = 0.f;
        const float4* q4  = (const float4*)&Qs[qi * KP];
        const float4* k04 = (const float4*)&Ks[(qi + lane) * KP];
        const float4* k14 = (const float4*)&Ks[(qi + 32 + lane) * KP];
        #pragma unroll
        for (int c = 0; c < 16; c++) {
            float4 qv = q4[c];
            float4 ka = k04[c];
            float4 kb = k14[c];
            d0 = fmaf(qv.x, ka.x, d0); d0 = fmaf(qv.y, ka.y, d0);
            d0 = fmaf(qv.z, ka.z, d0); d0 = fmaf(qv.w, ka.w, d0);
            d1 = fmaf(qv.x, kb.x, d1); d1 = fmaf(qv.y, kb.y, d1);
            d1 = fmaf(qv.z, kb.z, d1); d1 = fmaf(qv.w, kb.w, d1);
        }
        float s0 = v0 ? d0 : -1e30f;
        float s1 = v1 ? d1 : -1e30f;

        // 65th key: cooperative dot
        float part = Qs[qi * KP + lane]      * Ks[(qi + 64) * KP + lane]
                   + Qs[qi * KP + lane + 32] * Ks[(qi + 64) * KP + lane + 32];
        part += __shfl_xor_sync(0xffffffffu, part, 16);
        part += __shfl_xor_sync(0xffffffffu, part, 8);
        part += __shfl_xor_sync(0xffffffffu, part, 4);
        part += __shfl_xor_sync(0xffffffffu, part, 2);
        part += __shfl_xor_sync(0xffffffffu, part, 1);
        const bool v2 = (t + 32) < T_SEQ;
        float s2 = (lane == 0 && v2) ? part : -1e30f;

        // ---- softmax ----
        float m = fmaxf(fmaxf(s0, s1), s2);
        m = fmaxf(m, __shfl_xor_sync(0xffffffffu, m, 16));
        m = fmaxf(m, __shfl_xor_sync(0xffffffffu, m, 8));
        m = fmaxf(m, __shfl_xor_sync(0xffffffffu, m, 4));
        m = fmaxf(m, __shfl_xor_sync(0xffffffffu, m, 2));
        m = fmaxf(m, __shfl_xor_sync(0xffffffffu, m, 1));
        float p0 = __expf(s0 - m);
        float p1 = __expf(s1 - m);
        float p2 = __expf(s2 - m);
        float l = p0 + p1 + p2;
        l += __shfl_xor_sync(0xffffffffu, l, 16);
        l += __shfl_xor_sync(0xffffffffu, l, 8);
        l += __shfl_xor_sync(0xffffffffu, l, 4);
        l += __shfl_xor_sync(0xffffffffu, l, 2);
        l += __shfl_xor_sync(0xffffffffu, l, 1);
        float inv = 1.f / l;

        float* pw = &Ps[warp * 80];
        pw[lane]      = p0 * inv;
        pw[lane + 32] = p1 * inv;
        if (lane < 4) pw[64 + lane] = (lane == 0) ? p2 * inv : 0.f;
        __syncwarp();

        // ---- phase B: out = P.V (dims in lanes, interleaved V) ----
        float a0 = 0.f, a1 = 0.f;
        const float* vb = &Vs[qi * KP + 2 * lane];
        #pragma unroll
        for (int j4 = 0; j4 < 17; j4++) {
            float4 pf = *(const float4*)&pw[j4 * 4];
            float2 va = *(const float2*)&vb[(j4 * 4 + 0) * KP];
            float2 vb2 = *(const float2*)&vb[(j4 * 4 + 1) * KP];
            float2 vc = *(const float2*)&vb[(j4 * 4 + 2) * KP];
            float2 vd = *(const float2*)&vb[(j4 * 4 + 3) * KP];
            a0 = fmaf(pf.x, va.x, a0);  a1 = fmaf(pf.x, va.y, a1);
            a0 = fmaf(pf.y, vb2.x, a0); a1 = fmaf(pf.y, vb2.y, a1);
            a0 = fmaf(pf.z, vc.x, a0);  a1 = fmaf(pf.z, vc.y, a1);
            a0 = fmaf(pf.w, vd.x, a0);  a1 = fmaf(pf.w, vd.y, a1);
        }

        size_t off = ((size_t)(b * T_SEQ + t)) * D_MODEL + h * HD;
        outh[off + lane]      = __float2half_rn(a0);
        outh[off + lane + 32] = __float2half_rn(a1);
        __syncwarp();
    }
}

// ---------------------------------------------------------------------------
extern "C" void kernel_launch(void* const* d_in, const int* in_sizes, int n_in,
                              void* d_out, int out_size)
{
    const float* x    = (const float*)d_in[0];
    const float* Wqkv = (const float*)d_in[1];
    const float* bqkv = (const float*)d_in[2];
    const float* Wout = (const float*)d_in[3];
    const float* bout = (const float*)d_in[4];
    float* out = (float*)d_out;

    float* qkv_p;
    __half *xh, *wq, *wo, *ah;
    cudaGetSymbolAddress((void**)&qkv_p, g_qkv);
    cudaGetSymbolAddress((void**)&xh, g_xh);
    cudaGetSymbolAddress((void**)&wq, g_wq);
    cudaGetSymbolAddress((void**)&wo, g_wo);
    cudaGetSymbolAddress((void**)&ah, g_ah);

    cudaFuncSetAttribute(gemm_hmma, cudaFuncAttributeMaxDynamicSharedMemorySize, SMEM_BYTES);
    cudaFuncSetAttribute(attn_local, cudaFuncAttributeMaxDynamicSharedMemorySize, ATTN_SMEM);

    {   int n4 = (M_TOT * D_MODEL) / 4;
        conv_f16<<<(n4 + 255) / 256, 256>>>(x, xh, n4); }
    {   int n4 = (N_QKV * D_MODEL) / 4;
        conv_f16<<<(n4 + 255) / 256, 256>>>(Wqkv, wq, n4); }
    {   int n4 = (D_MODEL * D_MODEL) / 4;
        conv_f16<<<(n4 + 255) / 256, 256>>>(Wout, wo, n4); }

    // 1) QKV projection
    gemm_hmma<<<dim3(N_QKV / 128, M_TOT / 128), 256, SMEM_BYTES>>>(
        xh, wq, bqkv, qkv_p, N_QKV);

    // 2) local attention (fp16 output)
    attn_local<<<dim3(T_SEQ / QT, NH, BATCH), 256, ATTN_SMEM>>>(qkv_p, ah);

    // 3) output projection
    gemm_hmma<<<dim3(D_MODEL / 128, M_TOT / 128), 256, SMEM_BYTES>>>(
        ah, wo, bout, out, D_MODEL);
}

// round 8
// speedup vs baseline: 5.3081x; 1.2060x over previous
#include <cuda_runtime.h>
#include <cuda_fp16.h>
#include <cstdint>
#include <cstring>

#define T_SEQ 2048
#define D_MODEL 1024
#define NH 16
#define HD 64
#define BATCH 4
#define M_TOT (BATCH * T_SEQ)       // 8192
#define N_QKV (3 * D_MODEL)         // 3072

// ---------------- scratch (__device__ globals: allocation-free) -------------
__device__ __half g_qkvh[(size_t)M_TOT * N_QKV];        // 48 MB, fp16 qkv
__device__ __half g_xh[(size_t)M_TOT * D_MODEL];
__device__ __half g_wq[(size_t)N_QKV * D_MODEL];
__device__ __half g_wo[(size_t)D_MODEL * D_MODEL];
__device__ __half g_ah[(size_t)M_TOT * D_MODEL];

// ---------------- helpers ---------------------------------------------------
__device__ __forceinline__ uint32_t smem_u32(const void* p) {
    uint32_t a;
    asm("{ .reg .u64 t; cvta.to.shared.u64 t, %1; cvt.u32.u64 %0, t; }"
        : "=r"(a) : "l"(p));
    return a;
}
__device__ __forceinline__ void cp_async16(uint32_t smem_dst, const void* gmem_src) {
    asm volatile("cp.async.cg.shared.global [%0], [%1], 16;"
                 :: "r"(smem_dst), "l"(gmem_src) : "memory");
}
__device__ __forceinline__ void cp_commit() {
    asm volatile("cp.async.commit_group;" ::: "memory");
}
__device__ __forceinline__ void cp_wait1() {
    asm volatile("cp.async.wait_group 1;" ::: "memory");
}
__device__ __forceinline__ void ldsm_x4(uint32_t addr, uint32_t& r0, uint32_t& r1,
                                        uint32_t& r2, uint32_t& r3) {
    asm volatile("ldmatrix.sync.aligned.m8n8.x4.shared.b16 {%0,%1,%2,%3}, [%4];"
                 : "=r"(r0), "=r"(r1), "=r"(r2), "=r"(r3) : "r"(addr));
}
__device__ __forceinline__ void mma_f16(float* d, const uint32_t* a, const uint32_t* b) {
    asm volatile(
        "mma.sync.aligned.m16n8k16.row.col.f32.f16.f16.f32 "
        "{%0,%1,%2,%3}, {%4,%5,%6,%7}, {%8,%9}, {%0,%1,%2,%3};"
        : "+f"(d[0]), "+f"(d[1]), "+f"(d[2]), "+f"(d[3])
        : "r"(a[0]), "r"(a[1]), "r"(a[2]), "r"(a[3]), "r"(b[0]), "r"(b[1]));
}

// ---------------- fp32 -> fp16 convert ---------------------------------------
__global__ __launch_bounds__(256) void conv_f16(
    const float* __restrict__ in, __half* __restrict__ out, int n4)
{
    int i = blockIdx.x * blockDim.x + threadIdx.x;
    if (i >= n4) return;
    float4 v = ((const float4*)in)[i];
    __half h[4] = {__float2half_rn(v.x), __float2half_rn(v.y),
                   __float2half_rn(v.z), __float2half_rn(v.w)};
    *(uint2*)(out + 4 * (size_t)i) = *(uint2*)h;
}

// ---------------- HMMA GEMM: C = A @ B^T + bias (OT = float | __half) --------
#define KC 64
#define LDROW 144
#define TILE_B (128 * LDROW)         // 18432
#define STAGE_B (2 * TILE_B)         // 36864
#define SMEM_BYTES (3 * STAGE_B)     // 110592
#define NCHUNK (1024 / KC)           // 16

template <typename OT>
__global__ __launch_bounds__(256) void gemm_hmma(
    const __half* __restrict__ A, const __half* __restrict__ Bw,
    const float* __restrict__ bias, OT* __restrict__ C, int N)
{
    extern __shared__ char smem[];
    const int tid  = threadIdx.x;
    const int wid  = tid >> 5, lane = tid & 31;
    const int wm   = wid >> 1, wn = wid & 1;
    const int bn   = blockIdx.x * 128, bm = blockIdx.y * 128;
    const uint32_t sbase = smem_u32(smem);

    const char* gsrc[2];
    gsrc[0] = (const char*)A  + (size_t)bm * 2048;
    gsrc[1] = (const char*)Bw + (size_t)bn * 2048;

    int ld_which[8], ld_row[8], ld_c16[8];
    #pragma unroll
    for (int i = 0; i < 8; i++) {
        int idx = tid + i * 256;          // 0..2047
        ld_which[i] = idx >> 10;
        ld_row[i]   = (idx >> 3) & 127;
        ld_c16[i]   = idx & 7;
    }

    auto load_stage = [&](int chunk, int slot) {
        const size_t k0b = (size_t)chunk * (KC * 2);
        uint32_t sdst = sbase + slot * STAGE_B;
        #pragma unroll
        for (int i = 0; i < 8; i++) {
            const char* g = gsrc[ld_which[i]] + (size_t)ld_row[i] * 2048 + k0b + ld_c16[i] * 16;
            uint32_t s = sdst + ld_which[i] * TILE_B + ld_row[i] * LDROW + ld_c16[i] * 16;
            cp_async16(s, g);
        }
    };

    float acc[2][8][4];
    #pragma unroll
    for (int mt = 0; mt < 2; mt++)
        #pragma unroll
        for (int nt = 0; nt < 8; nt++)
            #pragma unroll
            for (int j = 0; j < 4; j++) acc[mt][nt][j] = 0.f;

    const uint32_t a_off = (uint32_t)(wm * 32 + (lane & 15)) * LDROW + (lane >> 4) * 16;
    const uint32_t b_off = (uint32_t)(wn * 64 + ((lane >> 4) & 1) * 8 + (lane & 7)) * LDROW
                         + ((lane >> 3) & 1) * 16;

    load_stage(0, 0); cp_commit();
    load_stage(1, 1); cp_commit();

    for (int c = 0; c < NCHUNK; c++) {
        const int slot = c % 3;
        cp_wait1();
        __syncthreads();
        if (c + 2 < NCHUNK) load_stage(c + 2, (c + 2) % 3);
        cp_commit();

        const uint32_t st = sbase + slot * STAGE_B;
        const uint32_t tA = st, tB = st + TILE_B;

        #pragma unroll
        for (int ks = 0; ks < 4; ks++) {
            const uint32_t kb = ks * 32;
            uint32_t aa[2][4], bb[4][4];
            #pragma unroll
            for (int mt = 0; mt < 2; mt++)
                ldsm_x4(tA + a_off + (uint32_t)mt * 16 * LDROW + kb,
                        aa[mt][0], aa[mt][1], aa[mt][2], aa[mt][3]);
            #pragma unroll
            for (int p = 0; p < 4; p++)
                ldsm_x4(tB + b_off + (uint32_t)p * 16 * LDROW + kb,
                        bb[p][0], bb[p][1], bb[p][2], bb[p][3]);
            #pragma unroll
            for (int mt = 0; mt < 2; mt++)
                #pragma unroll
                for (int nt = 0; nt < 8; nt++)
                    mma_f16(acc[mt][nt], aa[mt], &bb[nt >> 1][(nt & 1) * 2]);
        }
    }
    __syncthreads();

    // epilogue through smem for coalesced stores
    float* stage = (float*)smem;          // [128][132]
    #pragma unroll
    for (int mt = 0; mt < 2; mt++)
        #pragma unroll
        for (int nt = 0; nt < 8; nt++) {
            int row = wm * 32 + mt * 16 + (lane >> 2);
            int col = wn * 64 + nt * 8 + (lane & 3) * 2;
            stage[row * 132 + col]           = acc[mt][nt][0];
            stage[row * 132 + col + 1]       = acc[mt][nt][1];
            stage[(row + 8) * 132 + col]     = acc[mt][nt][2];
            stage[(row + 8) * 132 + col + 1] = acc[mt][nt][3];
        }
    __syncthreads();

    #pragma unroll
    for (int i = 0; i < 16; i++) {
        int idx = tid + i * 256;
        int row = idx >> 5;
        int c4  = (idx & 31) * 4;
        float4 bv = *(const float4*)(bias + bn + c4);
        float ox = stage[row * 132 + c4 + 0] + bv.x;
        float oy = stage[row * 132 + c4 + 1] + bv.y;
        float oz = stage[row * 132 + c4 + 2] + bv.z;
        float ow = stage[row * 132 + c4 + 3] + bv.w;
        if constexpr (sizeof(OT) == 4) {
            float4 o = {ox, oy, oz, ow};
            *(float4*)((float*)C + (size_t)(bm + row) * N + bn + c4) = o;
        } else {
            __half h4[4] = {__float2half_rn(ox), __float2half_rn(oy),
                            __float2half_rn(oz), __float2half_rn(ow)};
            *(uint2*)((__half*)C + (size_t)(bm + row) * N + bn + c4) = *(uint2*)h4;
        }
    }
}

// ---------------- local windowed attention (fp16 K/V in smem) ----------------
// Phase A: keys-in-lanes scores, K fp16 (half the smem-port bytes), Q fp32.
// Phase B: dims-in-lanes P.V, V interleaved half2 (dims d,d+32 adjacent).
#define QT 32
#define KT 96
#define KTV 100
#define KPH 72                        // half stride for Ks/Vs rows
#define QPF 68                        // float stride for Qs rows
// bytes: Ks 96*72*2 + Vs 100*72*2 + Qs 32*68*4 + Ps 8*80*4
#define ATTN_SMEM (96 * KPH * 2 + KTV * KPH * 2 + QT * QPF * 4 + 8 * 80 * 4)

__global__ __launch_bounds__(256) void attn_local(
    const __half* __restrict__ qkv, __half* __restrict__ outh)
{
    extern __shared__ char asmem[];
    __half* Ks = (__half*)asmem;                    // [96][72]
    __half* Vs = Ks + 96 * KPH;                     // [100][72] interleaved
    float*  Qs = (float*)(Vs + KTV * KPH);          // [32][68] pre-scaled
    float*  Ps = Qs + QT * QPF;                     // [8][80]

    const int b = blockIdx.z, h = blockIdx.y;
    const int t0 = blockIdx.x * QT;
    const int kbase = t0 - 32;
    const int tid = threadIdx.x;

    // ---- staging: K 768 tasks, V 384 tasks, Q 256 tasks ----
    #pragma unroll
    for (int i = 0; i < 6; i++) {
        int idx = tid + i * 256;                    // 0..1535
        if (idx < 768) {                            // K: row 0..95, 8x16B chunks
            int row = idx >> 3, c = idx & 7;
            int tk = kbase + row;
            uint4 v = {0u, 0u, 0u, 0u};
            if (tk >= 0 && tk < T_SEQ)
                v = ((const uint4*)(qkv + ((size_t)(b * T_SEQ + tk)) * N_QKV
                                    + D_MODEL + h * HD))[c];
            *(uint4*)(Ks + row * KPH + c * 8) = v;
        } else if (idx < 1152) {                    // V: row 0..95, 4 pair-slices
            int j = idx - 768;
            int row = j >> 2, c = j & 3;
            int tk = kbase + row;
            uint4 lo = {0u, 0u, 0u, 0u}, hi = {0u, 0u, 0u, 0u};
            if (tk >= 0 && tk < T_SEQ) {
                const __half* base = qkv + ((size_t)(b * T_SEQ + tk)) * N_QKV
                                   + 2 * D_MODEL + h * HD;
                lo = ((const uint4*)base)[c];
                hi = ((const uint4*)(base + 32))[c];
            }
            __half lh[8], hh[8], oo[16];
            memcpy(lh, &lo, 16); memcpy(hh, &hi, 16);
            #pragma unroll
            for (int k = 0; k < 8; k++) { oo[2 * k] = lh[k]; oo[2 * k + 1] = hh[k]; }
            uint4 o0, o1;
            memcpy(&o0, oo, 16); memcpy(&o1, oo + 8, 16);
            __half* dst = Vs + row * KPH + c * 16;
            ((uint4*)dst)[0] = o0; ((uint4*)dst)[1] = o1;
        } else if (idx < 1408) {                    // Q: row 0..31, 8-half chunks
            int j = idx - 1152;
            int row = j >> 3, c = j & 7;
            uint4 v = ((const uint4*)(qkv + ((size_t)(b * T_SEQ + t0 + row)) * N_QKV
                                      + h * HD))[c];
            __half qh[8]; memcpy(qh, &v, 16);
            float* dst = Qs + row * QPF + c * 8;
            #pragma unroll
            for (int k = 0; k < 8; k++) dst[k] = __half2float(qh[k]) * 0.125f;
        }
    }
    // zero V pad rows 96..99 (36 uint4)
    if (tid < 36) {
        int r = tid / 9, c = tid % 9;
        *(uint4*)(Vs + (96 + r) * KPH + c * 8) = make_uint4(0, 0, 0, 0);
    }
    __syncthreads();

    const int warp = tid >> 5, lane = tid & 31;

    #pragma unroll 1
    for (int qq = 0; qq < 4; qq++) {
        const int qi = warp * 4 + qq;
        const int t  = t0 + qi;

        // ---- phase A: scores (keys in lanes), fp16 K ----
        const bool v0 = (t - 32 + lane) >= 0;
        const bool v1 = (t + lane) < T_SEQ;
        float d0 = 0.f, d1 = 0.f;
        const uint4* k0p = (const uint4*)(Ks + (qi + lane) * KPH);
        const uint4* k1p = (const uint4*)(Ks + (qi + 32 + lane) * KPH);
        const float4* qf = (const float4*)(Qs + qi * QPF);
        #pragma unroll
        for (int i = 0; i < 8; i++) {
            uint4 ka = k0p[i], kb = k1p[i];
            float4 qa = qf[2 * i], qb = qf[2 * i + 1];
            const __half2* pa = (const __half2*)&ka;
            const __half2* pb = (const __half2*)&kb;
            float2 a0 = __half22float2(pa[0]), a1 = __half22float2(pa[1]);
            float2 a2 = __half22float2(pa[2]), a3 = __half22float2(pa[3]);
            float2 b0 = __half22float2(pb[0]), b1 = __half22float2(pb[1]);
            float2 b2 = __half22float2(pb[2]), b3 = __half22float2(pb[3]);
            d0 = fmaf(qa.x, a0.x, d0); d0 = fmaf(qa.y, a0.y, d0);
            d0 = fmaf(qa.z, a1.x, d0); d0 = fmaf(qa.w, a1.y, d0);
            d0 = fmaf(qb.x, a2.x, d0); d0 = fmaf(qb.y, a2.y, d0);
            d0 = fmaf(qb.z, a3.x, d0); d0 = fmaf(qb.w, a3.y, d0);
            d1 = fmaf(qa.x, b0.x, d1); d1 = fmaf(qa.y, b0.y, d1);
            d1 = fmaf(qa.z, b1.x, d1); d1 = fmaf(qa.w, b1.y, d1);
            d1 = fmaf(qb.x, b2.x, d1); d1 = fmaf(qb.y, b2.y, d1);
            d1 = fmaf(qb.z, b3.x, d1); d1 = fmaf(qb.w, b3.y, d1);
        }
        float s0 = v0 ? d0 : -1e30f;
        float s1 = v1 ? d1 : -1e30f;

        // 65th key: cooperative dot
        float part = Qs[qi * QPF + lane]      * __half2float(Ks[(qi + 64) * KPH + lane])
                   + Qs[qi * QPF + lane + 32] * __half2float(Ks[(qi + 64) * KPH + lane + 32]);
        part += __shfl_xor_sync(0xffffffffu, part, 16);
        part += __shfl_xor_sync(0xffffffffu, part, 8);
        part += __shfl_xor_sync(0xffffffffu, part, 4);
        part += __shfl_xor_sync(0xffffffffu, part, 2);
        part += __shfl_xor_sync(0xffffffffu, part, 1);
        const bool v2 = (t + 32) < T_SEQ;
        float s2 = (lane == 0 && v2) ? part : -1e30f;

        // ---- softmax ----
        float m = fmaxf(fmaxf(s0, s1), s2);
        m = fmaxf(m, __shfl_xor_sync(0xffffffffu, m, 16));
        m = fmaxf(m, __shfl_xor_sync(0xffffffffu, m, 8));
        m = fmaxf(m, __shfl_xor_sync(0xffffffffu, m, 4));
        m = fmaxf(m, __shfl_xor_sync(0xffffffffu, m, 2));
        m = fmaxf(m, __shfl_xor_sync(0xffffffffu, m, 1));
        float p0 = __expf(s0 - m);
        float p1 = __expf(s1 - m);
        float p2 = __expf(s2 - m);
        float l = p0 + p1 + p2;
        l += __shfl_xor_sync(0xffffffffu, l, 16);
        l += __shfl_xor_sync(0xffffffffu, l, 8);
        l += __shfl_xor_sync(0xffffffffu, l, 4);
        l += __shfl_xor_sync(0xffffffffu, l, 2);
        l += __shfl_xor_sync(0xffffffffu, l, 1);
        float inv = 1.f / l;

        float* pw = &Ps[warp * 80];
        pw[lane]      = p0 * inv;
        pw[lane + 32] = p1 * inv;
        if (lane < 4) pw[64 + lane] = (lane == 0) ? p2 * inv : 0.f;
        __syncwarp();

        // ---- phase B: out = P.V (dims in lanes, interleaved half2 V) ----
        float a0 = 0.f, a1 = 0.f;
        const __half2* vrow = (const __half2*)(Vs + qi * KPH) + lane;
        #pragma unroll
        for (int j4 = 0; j4 < 17; j4++) {
            float4 pf = *(const float4*)&pw[j4 * 4];
            float2 fa = __half22float2(vrow[(j4 * 4 + 0) * (KPH / 2)]);
            float2 fb = __half22float2(vrow[(j4 * 4 + 1) * (KPH / 2)]);
            float2 fc = __half22float2(vrow[(j4 * 4 + 2) * (KPH / 2)]);
            float2 fd = __half22float2(vrow[(j4 * 4 + 3) * (KPH / 2)]);
            a0 = fmaf(pf.x, fa.x, a0); a1 = fmaf(pf.x, fa.y, a1);
            a0 = fmaf(pf.y, fb.x, a0); a1 = fmaf(pf.y, fb.y, a1);
            a0 = fmaf(pf.z, fc.x, a0); a1 = fmaf(pf.z, fc.y, a1);
            a0 = fmaf(pf.w, fd.x, a0); a1 = fmaf(pf.w, fd.y, a1);
        }

        size_t off = ((size_t)(b * T_SEQ + t)) * D_MODEL + h * HD;
        outh[off + lane]      = __float2half_rn(a0);
        outh[off + lane + 32] = __float2half_rn(a1);
        __syncwarp();
    }
}

// ---------------------------------------------------------------------------
extern "C" void kernel_launch(void* const* d_in, const int* in_sizes, int n_in,
                              void* d_out, int out_size)
{
    const float* x    = (const float*)d_in[0];
    const float* Wqkv = (const float*)d_in[1];
    const float* bqkv = (const float*)d_in[2];
    const float* Wout = (const float*)d_in[3];
    const float* bout = (const float*)d_in[4];
    float* out = (float*)d_out;

    __half *qkvh, *xh, *wq, *wo, *ah;
    cudaGetSymbolAddress((void**)&qkvh, g_qkvh);
    cudaGetSymbolAddress((void**)&xh, g_xh);
    cudaGetSymbolAddress((void**)&wq, g_wq);
    cudaGetSymbolAddress((void**)&wo, g_wo);
    cudaGetSymbolAddress((void**)&ah, g_ah);

    cudaFuncSetAttribute(gemm_hmma<__half>, cudaFuncAttributeMaxDynamicSharedMemorySize, SMEM_BYTES);
    cudaFuncSetAttribute(gemm_hmma<float>,  cudaFuncAttributeMaxDynamicSharedMemorySize, SMEM_BYTES);
    cudaFuncSetAttribute(attn_local, cudaFuncAttributeMaxDynamicSharedMemorySize, ATTN_SMEM);

    {   int n4 = (M_TOT * D_MODEL) / 4;
        conv_f16<<<(n4 + 255) / 256, 256>>>(x, xh, n4); }
    {   int n4 = (N_QKV * D_MODEL) / 4;
        conv_f16<<<(n4 + 255) / 256, 256>>>(Wqkv, wq, n4); }
    {   int n4 = (D_MODEL * D_MODEL) / 4;
        conv_f16<<<(n4 + 255) / 256, 256>>>(Wout, wo, n4); }

    // 1) QKV projection -> fp16 qkv
    gemm_hmma<__half><<<dim3(N_QKV / 128, M_TOT / 128), 256, SMEM_BYTES>>>(
        xh, wq, bqkv, qkvh, N_QKV);

    // 2) local attention (fp16 in/out)
    attn_local<<<dim3(T_SEQ / QT, NH, BATCH), 256, ATTN_SMEM>>>(qkvh, ah);

    // 3) output projection -> fp32 final
    gemm_hmma<float><<<dim3(D_MODEL / 128, M_TOT / 128), 256, SMEM_BYTES>>>(
        ah, wo, bout, out, D_MODEL);
}

// round 9
// speedup vs baseline: 5.3650x; 1.0107x over previous
#include <cuda_runtime.h>
#include <cuda_fp16.h>
#include <cstdint>
#include <cstring>

#define T_SEQ 2048
#define D_MODEL 1024
#define NH 16
#define HD 64
#define BATCH 4
#define M_TOT (BATCH * T_SEQ)       // 8192
#define N_QKV (3 * D_MODEL)         // 3072

// ---------------- scratch (__device__ globals: allocation-free) -------------
__device__ __half g_qkvh[(size_t)M_TOT * N_QKV];        // 48 MB, fp16 qkv
__device__ __half g_xh[(size_t)M_TOT * D_MODEL];
__device__ __half g_wq[(size_t)N_QKV * D_MODEL];
__device__ __half g_wo[(size_t)D_MODEL * D_MODEL];
__device__ __half g_ah[(size_t)M_TOT * D_MODEL];

// ---------------- helpers ---------------------------------------------------
__device__ __forceinline__ uint32_t smem_u32(const void* p) {
    uint32_t a;
    asm("{ .reg .u64 t; cvta.to.shared.u64 t, %1; cvt.u32.u64 %0, t; }"
        : "=r"(a) : "l"(p));
    return a;
}
__device__ __forceinline__ void cp_async16(uint32_t smem_dst, const void* gmem_src) {
    asm volatile("cp.async.cg.shared.global [%0], [%1], 16;"
                 :: "r"(smem_dst), "l"(gmem_src) : "memory");
}
__device__ __forceinline__ void cp_commit() {
    asm volatile("cp.async.commit_group;" ::: "memory");
}
__device__ __forceinline__ void cp_wait1() {
    asm volatile("cp.async.wait_group 1;" ::: "memory");
}
__device__ __forceinline__ void ldsm_x4(uint32_t addr, uint32_t& r0, uint32_t& r1,
                                        uint32_t& r2, uint32_t& r3) {
    asm volatile("ldmatrix.sync.aligned.m8n8.x4.shared.b16 {%0,%1,%2,%3}, [%4];"
                 : "=r"(r0), "=r"(r1), "=r"(r2), "=r"(r3) : "r"(addr));
}
__device__ __forceinline__ void mma_f16(float* d, const uint32_t* a, const uint32_t* b) {
    asm volatile(
        "mma.sync.aligned.m16n8k16.row.col.f32.f16.f16.f32 "
        "{%0,%1,%2,%3}, {%4,%5,%6,%7}, {%8,%9}, {%0,%1,%2,%3};"
        : "+f"(d[0]), "+f"(d[1]), "+f"(d[2]), "+f"(d[3])
        : "r"(a[0]), "r"(a[1]), "r"(a[2]), "r"(a[3]), "r"(b[0]), "r"(b[1]));
}

// ---------------- fused fp32 -> fp16 convert (x, Wqkv, Wout in one grid) -----
#define NX4 ((M_TOT * D_MODEL) / 4)             // 2097152
#define NWQ4 ((N_QKV * D_MODEL) / 4)            // 786432
#define NWO4 ((D_MODEL * D_MODEL) / 4)          // 262144

__global__ __launch_bounds__(256) void conv_all(
    const float* __restrict__ x, const float* __restrict__ wq_in,
    const float* __restrict__ wo_in,
    __half* __restrict__ xh, __half* __restrict__ wqh, __half* __restrict__ woh)
{
    int i = blockIdx.x * blockDim.x + threadIdx.x;
    const float* src; __half* dst; int j;
    if (i < NX4)                       { src = x;     dst = xh;  j = i; }
    else if (i < NX4 + NWQ4)           { src = wq_in; dst = wqh; j = i - NX4; }
    else if (i < NX4 + NWQ4 + NWO4)    { src = wo_in; dst = woh; j = i - NX4 - NWQ4; }
    else return;
    float4 v = ((const float4*)src)[j];
    __half h[4] = {__float2half_rn(v.x), __float2half_rn(v.y),
                   __float2half_rn(v.z), __float2half_rn(v.w)};
    *(uint2*)(dst + 4 * (size_t)j) = *(uint2*)h;
}

// ---------------- HMMA GEMM: C = A @ B^T + bias (OT = float | __half) --------
// Fragment double-buffering across ks steps hides LDSM latency under MMAs.
#define KC 64
#define LDROW 144
#define TILE_B (128 * LDROW)         // 18432
#define STAGE_B (2 * TILE_B)         // 36864
#define SMEM_BYTES (3 * STAGE_B)     // 110592
#define NCHUNK (1024 / KC)           // 16

template <typename OT>
__global__ __launch_bounds__(256, 2) void gemm_hmma(
    const __half* __restrict__ A, const __half* __restrict__ Bw,
    const float* __restrict__ bias, OT* __restrict__ C, int N)
{
    extern __shared__ char smem[];
    const int tid  = threadIdx.x;
    const int wid  = tid >> 5, lane = tid & 31;
    const int wm   = wid >> 1, wn = wid & 1;
    const int bn   = blockIdx.x * 128, bm = blockIdx.y * 128;
    const uint32_t sbase = smem_u32(smem);

    const char* gsrc[2];
    gsrc[0] = (const char*)A  + (size_t)bm * 2048;
    gsrc[1] = (const char*)Bw + (size_t)bn * 2048;

    int ld_which[8], ld_row[8], ld_c16[8];
    #pragma unroll
    for (int i = 0; i < 8; i++) {
        int idx = tid + i * 256;          // 0..2047
        ld_which[i] = idx >> 10;
        ld_row[i]   = (idx >> 3) & 127;
        ld_c16[i]   = idx & 7;
    }

    auto load_stage = [&](int chunk, int slot) {
        const size_t k0b = (size_t)chunk * (KC * 2);
        uint32_t sdst = sbase + slot * STAGE_B;
        #pragma unroll
        for (int i = 0; i < 8; i++) {
            const char* g = gsrc[ld_which[i]] + (size_t)ld_row[i] * 2048 + k0b + ld_c16[i] * 16;
            uint32_t s = sdst + ld_which[i] * TILE_B + ld_row[i] * LDROW + ld_c16[i] * 16;
            cp_async16(s, g);
        }
    };

    float acc[2][8][4];
    #pragma unroll
    for (int mt = 0; mt < 2; mt++)
        #pragma unroll
        for (int nt = 0; nt < 8; nt++)
            #pragma unroll
            for (int j = 0; j < 4; j++) acc[mt][nt][j] = 0.f;

    const uint32_t a_off = (uint32_t)(wm * 32 + (lane & 15)) * LDROW + (lane >> 4) * 16;
    const uint32_t b_off = (uint32_t)(wn * 64 + ((lane >> 4) & 1) * 8 + (lane & 7)) * LDROW
                         + ((lane >> 3) & 1) * 16;

    load_stage(0, 0); cp_commit();
    load_stage(1, 1); cp_commit();

    uint32_t aa[2][2][4], bb[2][4][4];    // [buf][frag][regs]

    for (int c = 0; c < NCHUNK; c++) {
        const int slot = c % 3;
        cp_wait1();
        __syncthreads();
        if (c + 2 < NCHUNK) load_stage(c + 2, (c + 2) % 3);
        cp_commit();

        const uint32_t st = sbase + slot * STAGE_B;
        const uint32_t tA = st, tB = st + TILE_B;

        // prologue: fragments for ks=0
        #pragma unroll
        for (int mt = 0; mt < 2; mt++)
            ldsm_x4(tA + a_off + (uint32_t)mt * 16 * LDROW,
                    aa[0][mt][0], aa[0][mt][1], aa[0][mt][2], aa[0][mt][3]);
        #pragma unroll
        for (int p = 0; p < 4; p++)
            ldsm_x4(tB + b_off + (uint32_t)p * 16 * LDROW,
                    bb[0][p][0], bb[0][p][1], bb[0][p][2], bb[0][p][3]);

        #pragma unroll
        for (int ks = 0; ks < 4; ks++) {
            const int cur = ks & 1, nxt = cur ^ 1;
            if (ks < 3) {                 // prefetch fragments for ks+1
                const uint32_t kb = (ks + 1) * 32;
                #pragma unroll
                for (int mt = 0; mt < 2; mt++)
                    ldsm_x4(tA + a_off + (uint32_t)mt * 16 * LDROW + kb,
                            aa[nxt][mt][0], aa[nxt][mt][1], aa[nxt][mt][2], aa[nxt][mt][3]);
                #pragma unroll
                for (int p = 0; p < 4; p++)
                    ldsm_x4(tB + b_off + (uint32_t)p * 16 * LDROW + kb,
                            bb[nxt][p][0], bb[nxt][p][1], bb[nxt][p][2], bb[nxt][p][3]);
            }
            #pragma unroll
            for (int mt = 0; mt < 2; mt++)
                #pragma unroll
                for (int nt = 0; nt < 8; nt++)
                    mma_f16(acc[mt][nt], aa[cur][mt], &bb[cur][nt >> 1][(nt & 1) * 2]);
        }
    }
    __syncthreads();

    // epilogue through smem for coalesced stores
    float* stage = (float*)smem;          // [128][132]
    #pragma unroll
    for (int mt = 0; mt < 2; mt++)
        #pragma unroll
        for (int nt = 0; nt < 8; nt++) {
            int row = wm * 32 + mt * 16 + (lane >> 2);
            int col = wn * 64 + nt * 8 + (lane & 3) * 2;
            stage[row * 132 + col]           = acc[mt][nt][0];
            stage[row * 132 + col + 1]       = acc[mt][nt][1];
            stage[(row + 8) * 132 + col]     = acc[mt][nt][2];
            stage[(row + 8) * 132 + col + 1] = acc[mt][nt][3];
        }
    __syncthreads();

    #pragma unroll
    for (int i = 0; i < 16; i++) {
        int idx = tid + i * 256;
        int row = idx >> 5;
        int c4  = (idx & 31) * 4;
        float4 bv = *(const float4*)(bias + bn + c4);
        float ox = stage[row * 132 + c4 + 0] + bv.x;
        float oy = stage[row * 132 + c4 + 1] + bv.y;
        float oz = stage[row * 132 + c4 + 2] + bv.z;
        float ow = stage[row * 132 + c4 + 3] + bv.w;
        if constexpr (sizeof(OT) == 4) {
            float4 o = {ox, oy, oz, ow};
            *(float4*)((float*)C + (size_t)(bm + row) * N + bn + c4) = o;
        } else {
            __half h4[4] = {__float2half_rn(ox), __float2half_rn(oy),
                            __float2half_rn(oz), __float2half_rn(ow)};
            *(uint2*)((__half*)C + (size_t)(bm + row) * N + bn + c4) = *(uint2*)h4;
        }
    }
}

// ---------------- local windowed attention (fp16 K/V in smem) ----------------
#define QT 32
#define KT 96
#define KTV 100
#define KPH 72                        // half stride for Ks/Vs rows
#define QPF 68                        // float stride for Qs rows
#define ATTN_SMEM (96 * KPH * 2 + KTV * KPH * 2 + QT * QPF * 4 + 8 * 80 * 4)

__global__ __launch_bounds__(256) void attn_local(
    const __half* __restrict__ qkv, __half* __restrict__ outh)
{
    extern __shared__ char asmem[];
    __half* Ks = (__half*)asmem;                    // [96][72]
    __half* Vs = Ks + 96 * KPH;                     // [100][72] interleaved
    float*  Qs = (float*)(Vs + KTV * KPH);          // [32][68] pre-scaled
    float*  Ps = Qs + QT * QPF;                     // [8][80]

    const int b = blockIdx.z, h = blockIdx.y;
    const int t0 = blockIdx.x * QT;
    const int kbase = t0 - 32;
    const int tid = threadIdx.x;

    #pragma unroll
    for (int i = 0; i < 6; i++) {
        int idx = tid + i * 256;                    // 0..1535
        if (idx < 768) {                            // K
            int row = idx >> 3, c = idx & 7;
            int tk = kbase + row;
            uint4 v = {0u, 0u, 0u, 0u};
            if (tk >= 0 && tk < T_SEQ)
                v = ((const uint4*)(qkv + ((size_t)(b * T_SEQ + tk)) * N_QKV
                                    + D_MODEL + h * HD))[c];
            *(uint4*)(Ks + row * KPH + c * 8) = v;
        } else if (idx < 1152) {                    // V interleaved
            int j = idx - 768;
            int row = j >> 2, c = j & 3;
            int tk = kbase + row;
            uint4 lo = {0u, 0u, 0u, 0u}, hi = {0u, 0u, 0u, 0u};
            if (tk >= 0 && tk < T_SEQ) {
                const __half* base = qkv + ((size_t)(b * T_SEQ + tk)) * N_QKV
                                   + 2 * D_MODEL + h * HD;
                lo = ((const uint4*)base)[c];
                hi = ((const uint4*)(base + 32))[c];
            }
            __half lh[8], hh[8], oo[16];
            memcpy(lh, &lo, 16); memcpy(hh, &hi, 16);
            #pragma unroll
            for (int k = 0; k < 8; k++) { oo[2 * k] = lh[k]; oo[2 * k + 1] = hh[k]; }
            uint4 o0, o1;
            memcpy(&o0, oo, 16); memcpy(&o1, oo + 8, 16);
            __half* dst = Vs + row * KPH + c * 16;
            ((uint4*)dst)[0] = o0; ((uint4*)dst)[1] = o1;
        } else if (idx < 1408) {                    // Q pre-scaled fp32
            int j = idx - 1152;
            int row = j >> 3, c = j & 7;
            uint4 v = ((const uint4*)(qkv + ((size_t)(b * T_SEQ + t0 + row)) * N_QKV
                                      + h * HD))[c];
            __half qh[8]; memcpy(qh, &v, 16);
            float* dst = Qs + row * QPF + c * 8;
            #pragma unroll
            for (int k = 0; k < 8; k++) dst[k] = __half2float(qh[k]) * 0.125f;
        }
    }
    if (tid < 36) {
        int r = tid / 9, c = tid % 9;
        *(uint4*)(Vs + (96 + r) * KPH + c * 8) = make_uint4(0, 0, 0, 0);
    }
    __syncthreads();

    const int warp = tid >> 5, lane = tid & 31;

    #pragma unroll 1
    for (int qq = 0; qq < 4; qq++) {
        const int qi = warp * 4 + qq;
        const int t  = t0 + qi;

        const bool v0 = (t - 32 + lane) >= 0;
        const bool v1 = (t + lane) < T_SEQ;
        float d0 = 0.f, d1 = 0.f;
        const uint4* k0p = (const uint4*)(Ks + (qi + lane) * KPH);
        const uint4* k1p = (const uint4*)(Ks + (qi + 32 + lane) * KPH);
        const float4* qf = (const float4*)(Qs + qi * QPF);
        #pragma unroll
        for (int i = 0; i < 8; i++) {
            uint4 ka = k0p[i], kb = k1p[i];
            float4 qa = qf[2 * i], qb = qf[2 * i + 1];
            const __half2* pa = (const __half2*)&ka;
            const __half2* pb = (const __half2*)&kb;
            float2 a0 = __half22float2(pa[0]), a1 = __half22float2(pa[1]);
            float2 a2 = __half22float2(pa[2]), a3 = __half22float2(pa[3]);
            float2 b0 = __half22float2(pb[0]), b1 = __half22float2(pb[1]);
            float2 b2 = __half22float2(pb[2]), b3 = __half22float2(pb[3]);
            d0 = fmaf(qa.x, a0.x, d0); d0 = fmaf(qa.y, a0.y, d0);
            d0 = fmaf(qa.z, a1.x, d0); d0 = fmaf(qa.w, a1.y, d0);
            d0 = fmaf(qb.x, a2.x, d0); d0 = fmaf(qb.y, a2.y, d0);
            d0 = fmaf(qb.z, a3.x, d0); d0 = fmaf(qb.w, a3.y, d0);
            d1 = fmaf(qa.x, b0.x, d1); d1 = fmaf(qa.y, b0.y, d1);
            d1 = fmaf(qa.z, b1.x, d1); d1 = fmaf(qa.w, b1.y, d1);
            d1 = fmaf(qb.x, b2.x, d1); d1 = fmaf(qb.y, b2.y, d1);
            d1 = fmaf(qb.z, b3.x, d1); d1 = fmaf(qb.w, b3.y, d1);
        }
        float s0 = v0 ? d0 : -1e30f;
        float s1 = v1 ? d1 : -1e30f;

        float part = Qs[qi * QPF + lane]      * __half2float(Ks[(qi + 64) * KPH + lane])
                   + Qs[qi * QPF + lane + 32] * __half2float(Ks[(qi + 64) * KPH + lane + 32]);
        part += __shfl_xor_sync(0xffffffffu, part, 16);
        part += __shfl_xor_sync(0xffffffffu, part, 8);
        part += __shfl_xor_sync(0xffffffffu, part, 4);
        part += __shfl_xor_sync(0xffffffffu, part, 2);
        part += __shfl_xor_sync(0xffffffffu, part, 1);
        const bool v2 = (t + 32) < T_SEQ;
        float s2 = (lane == 0 && v2) ? part : -1e30f;

        float m = fmaxf(fmaxf(s0, s1), s2);
        m = fmaxf(m, __shfl_xor_sync(0xffffffffu, m, 16));
        m = fmaxf(m, __shfl_xor_sync(0xffffffffu, m, 8));
        m = fmaxf(m, __shfl_xor_sync(0xffffffffu, m, 4));
        m = fmaxf(m, __shfl_xor_sync(0xffffffffu, m, 2));
        m = fmaxf(m, __shfl_xor_sync(0xffffffffu, m, 1));
        float p0 = __expf(s0 - m);
        float p1 = __expf(s1 - m);
        float p2 = __expf(s2 - m);
        float l = p0 + p1 + p2;
        l += __shfl_xor_sync(0xffffffffu, l, 16);
        l += __shfl_xor_sync(0xffffffffu, l, 8);
        l += __shfl_xor_sync(0xffffffffu, l, 4);
        l += __shfl_xor_sync(0xffffffffu, l, 2);
        l += __shfl_xor_sync(0xffffffffu, l, 1);
        float inv = 1.f / l;

        float* pw = &Ps[warp * 80];
        pw[lane]      = p0 * inv;
        pw[lane + 32] = p1 * inv;
        if (lane < 4) pw[64 + lane] = (lane == 0) ? p2 * inv : 0.f;
        __syncwarp();

        float a0 = 0.f, a1 = 0.f;
        const __half2* vrow = (const __half2*)(Vs + qi * KPH) + lane;
        #pragma unroll
        for (int j4 = 0; j4 < 17; j4++) {
            float4 pf = *(const float4*)&pw[j4 * 4];
            float2 fa = __half22float2(vrow[(j4 * 4 + 0) * (KPH / 2)]);
            float2 fb = __half22float2(vrow[(j4 * 4 + 1) * (KPH / 2)]);
            float2 fc = __half22float2(vrow[(j4 * 4 + 2) * (KPH / 2)]);
            float2 fd = __half22float2(vrow[(j4 * 4 + 3) * (KPH / 2)]);
            a0 = fmaf(pf.x, fa.x, a0); a1 = fmaf(pf.x, fa.y, a1);
            a0 = fmaf(pf.y, fb.x, a0); a1 = fmaf(pf.y, fb.y, a1);
            a0 = fmaf(pf.z, fc.x, a0); a1 = fmaf(pf.z, fc.y, a1);
            a0 = fmaf(pf.w, fd.x, a0); a1 = fmaf(pf.w, fd.y, a1);
        }

        size_t off = ((size_t)(b * T_SEQ + t)) * D_MODEL + h * HD;
        outh[off + lane]      = __float2half_rn(a0);
        outh[off + lane + 32] = __float2half_rn(a1);
        __syncwarp();
    }
}

// ---------------------------------------------------------------------------
extern "C" void kernel_launch(void* const* d_in, const int* in_sizes, int n_in,
                              void* d_out, int out_size)
{
    const float* x    = (const float*)d_in[0];
    const float* Wqkv = (const float*)d_in[1];
    const float* bqkv = (const float*)d_in[2];
    const float* Wout = (const float*)d_in[3];
    const float* bout = (const float*)d_in[4];
    float* out = (float*)d_out;

    __half *qkvh, *xh, *wq, *wo, *ah;
    cudaGetSymbolAddress((void**)&qkvh, g_qkvh);
    cudaGetSymbolAddress((void**)&xh, g_xh);
    cudaGetSymbolAddress((void**)&wq, g_wq);
    cudaGetSymbolAddress((void**)&wo, g_wo);
    cudaGetSymbolAddress((void**)&ah, g_ah);

    cudaFuncSetAttribute(gemm_hmma<__half>, cudaFuncAttributeMaxDynamicSharedMemorySize, SMEM_BYTES);
    cudaFuncSetAttribute(gemm_hmma<float>,  cudaFuncAttributeMaxDynamicSharedMemorySize, SMEM_BYTES);
    cudaFuncSetAttribute(attn_local, cudaFuncAttributeMaxDynamicSharedMemorySize, ATTN_SMEM);

    // 0) fused converts
    {
        int total = NX4 + NWQ4 + NWO4;
        conv_all<<<(total + 255) / 256, 256>>>(x, Wqkv, Wout, xh, wq, wo);
    }

    // 1) QKV projection -> fp16 qkv
    gemm_hmma<__half><<<dim3(N_QKV / 128, M_TOT / 128), 256, SMEM_BYTES>>>(
        xh, wq, bqkv, qkvh, N_QKV);

    // 2) local attention (fp16 in/out)
    attn_local<<<dim3(T_SEQ / QT, NH, BATCH), 256, ATTN_SMEM>>>(qkvh, ah);

    // 3) output projection -> fp32 final
    gemm_hmma<float><<<dim3(D_MODEL / 128, M_TOT / 128), 256, SMEM_BYTES>>>(
        ah, wo, bout, out, D_MODEL);
}

// round 10
// speedup vs baseline: 5.3668x; 1.0003x over previous
#include <cuda_runtime.h>
#include <cuda_fp16.h>
#include <cstdint>
#include <cstring>

#define T_SEQ 2048
#define D_MODEL 1024
#define NH 16
#define HD 64
#define BATCH 4
#define M_TOT (BATCH * T_SEQ)       // 8192
#define N_QKV (3 * D_MODEL)         // 3072

// ---------------- scratch (__device__ globals: allocation-free) -------------
__device__ __half g_qkvh[(size_t)M_TOT * N_QKV];        // 48 MB, fp16 qkv
__device__ __half g_xh[(size_t)M_TOT * D_MODEL];
__device__ __half g_wq[(size_t)N_QKV * D_MODEL];
__device__ __half g_wo[(size_t)D_MODEL * D_MODEL];
__device__ __half g_ah[(size_t)M_TOT * D_MODEL];

// ---------------- helpers ---------------------------------------------------
__device__ __forceinline__ uint32_t smem_u32(const void* p) {
    uint32_t a;
    asm("{ .reg .u64 t; cvta.to.shared.u64 t, %1; cvt.u32.u64 %0, t; }"
        : "=r"(a) : "l"(p));
    return a;
}
__device__ __forceinline__ void cp_async16(uint32_t smem_dst, const void* gmem_src) {
    asm volatile("cp.async.cg.shared.global [%0], [%1], 16;"
                 :: "r"(smem_dst), "l"(gmem_src) : "memory");
}
__device__ __forceinline__ void cp_commit() {
    asm volatile("cp.async.commit_group;" ::: "memory");
}
__device__ __forceinline__ void cp_wait1() {
    asm volatile("cp.async.wait_group 1;" ::: "memory");
}
__device__ __forceinline__ void ldsm_x4(uint32_t addr, uint32_t& r0, uint32_t& r1,
                                        uint32_t& r2, uint32_t& r3) {
    asm volatile("ldmatrix.sync.aligned.m8n8.x4.shared.b16 {%0,%1,%2,%3}, [%4];"
                 : "=r"(r0), "=r"(r1), "=r"(r2), "=r"(r3) : "r"(addr));
}
__device__ __forceinline__ void mma_f16(float* d, const uint32_t* a, const uint32_t* b) {
    asm volatile(
        "mma.sync.aligned.m16n8k16.row.col.f32.f16.f16.f32 "
        "{%0,%1,%2,%3}, {%4,%5,%6,%7}, {%8,%9}, {%0,%1,%2,%3};"
        : "+f"(d[0]), "+f"(d[1]), "+f"(d[2]), "+f"(d[3])
        : "r"(a[0]), "r"(a[1]), "r"(a[2]), "r"(a[3]), "r"(b[0]), "r"(b[1]));
}

// ---------------- fused fp32 -> fp16 convert (x, Wqkv, Wout in one grid) -----
#define NX4 ((M_TOT * D_MODEL) / 4)             // 2097152
#define NWQ4 ((N_QKV * D_MODEL) / 4)            // 786432
#define NWO4 ((D_MODEL * D_MODEL) / 4)          // 262144

__global__ __launch_bounds__(256) void conv_all(
    const float* __restrict__ x, const float* __restrict__ wq_in,
    const float* __restrict__ wo_in,
    __half* __restrict__ xh, __half* __restrict__ wqh, __half* __restrict__ woh)
{
    int i = blockIdx.x * blockDim.x + threadIdx.x;
    const float* src; __half* dst; int j;
    if (i < NX4)                       { src = x;     dst = xh;  j = i; }
    else if (i < NX4 + NWQ4)           { src = wq_in; dst = wqh; j = i - NX4; }
    else if (i < NX4 + NWQ4 + NWO4)    { src = wo_in; dst = woh; j = i - NX4 - NWQ4; }
    else return;
    float4 v = ((const float4*)src)[j];
    __half h[4] = {__float2half_rn(v.x), __float2half_rn(v.y),
                   __float2half_rn(v.z), __float2half_rn(v.w)};
    *(uint2*)(dst + 4 * (size_t)j) = *(uint2*)h;
}

// ---------------- HMMA GEMM: C = A @ B^T + bias (OT = float | __half) --------
#define KC 64
#define LDROW 144
#define TILE_B (128 * LDROW)         // 18432
#define STAGE_B (2 * TILE_B)         // 36864
#define SMEM_BYTES (3 * STAGE_B)     // 110592
#define NCHUNK (1024 / KC)           // 16

template <typename OT>
__global__ __launch_bounds__(256, 2) void gemm_hmma(
    const __half* __restrict__ A, const __half* __restrict__ Bw,
    const float* __restrict__ bias, OT* __restrict__ C, int N)
{
    extern __shared__ char smem[];
    const int tid  = threadIdx.x;
    const int wid  = tid >> 5, lane = tid & 31;
    const int wm   = wid >> 1, wn = wid & 1;
    const int bn   = blockIdx.x * 128, bm = blockIdx.y * 128;
    const uint32_t sbase = smem_u32(smem);

    const char* gsrc[2];
    gsrc[0] = (const char*)A  + (size_t)bm * 2048;
    gsrc[1] = (const char*)Bw + (size_t)bn * 2048;

    int ld_which[8], ld_row[8], ld_c16[8];
    #pragma unroll
    for (int i = 0; i < 8; i++) {
        int idx = tid + i * 256;          // 0..2047
        ld_which[i] = idx >> 10;
        ld_row[i]   = (idx >> 3) & 127;
        ld_c16[i]   = idx & 7;
    }

    auto load_stage = [&](int chunk, int slot) {
        const size_t k0b = (size_t)chunk * (KC * 2);
        uint32_t sdst = sbase + slot * STAGE_B;
        #pragma unroll
        for (int i = 0; i < 8; i++) {
            const char* g = gsrc[ld_which[i]] + (size_t)ld_row[i] * 2048 + k0b + ld_c16[i] * 16;
            uint32_t s = sdst + ld_which[i] * TILE_B + ld_row[i] * LDROW + ld_c16[i] * 16;
            cp_async16(s, g);
        }
    };

    float acc[2][8][4];
    #pragma unroll
    for (int mt = 0; mt < 2; mt++)
        #pragma unroll
        for (int nt = 0; nt < 8; nt++)
            #pragma unroll
            for (int j = 0; j < 4; j++) acc[mt][nt][j] = 0.f;

    const uint32_t a_off = (uint32_t)(wm * 32 + (lane & 15)) * LDROW + (lane >> 4) * 16;
    const uint32_t b_off = (uint32_t)(wn * 64 + ((lane >> 4) & 1) * 8 + (lane & 7)) * LDROW
                         + ((lane >> 3) & 1) * 16;

    load_stage(0, 0); cp_commit();
    load_stage(1, 1); cp_commit();

    uint32_t aa[2][2][4], bb[2][4][4];    // [buf][frag][regs]

    for (int c = 0; c < NCHUNK; c++) {
        const int slot = c % 3;
        cp_wait1();
        __syncthreads();
        if (c + 2 < NCHUNK) load_stage(c + 2, (c + 2) % 3);
        cp_commit();

        const uint32_t st = sbase + slot * STAGE_B;
        const uint32_t tA = st, tB = st + TILE_B;

        #pragma unroll
        for (int mt = 0; mt < 2; mt++)
            ldsm_x4(tA + a_off + (uint32_t)mt * 16 * LDROW,
                    aa[0][mt][0], aa[0][mt][1], aa[0][mt][2], aa[0][mt][3]);
        #pragma unroll
        for (int p = 0; p < 4; p++)
            ldsm_x4(tB + b_off + (uint32_t)p * 16 * LDROW,
                    bb[0][p][0], bb[0][p][1], bb[0][p][2], bb[0][p][3]);

        #pragma unroll
        for (int ks = 0; ks < 4; ks++) {
            const int cur = ks & 1, nxt = cur ^ 1;
            if (ks < 3) {
                const uint32_t kb = (ks + 1) * 32;
                #pragma unroll
                for (int mt = 0; mt < 2; mt++)
                    ldsm_x4(tA + a_off + (uint32_t)mt * 16 * LDROW + kb,
                            aa[nxt][mt][0], aa[nxt][mt][1], aa[nxt][mt][2], aa[nxt][mt][3]);
                #pragma unroll
                for (int p = 0; p < 4; p++)
                    ldsm_x4(tB + b_off + (uint32_t)p * 16 * LDROW + kb,
                            bb[nxt][p][0], bb[nxt][p][1], bb[nxt][p][2], bb[nxt][p][3]);
            }
            #pragma unroll
            for (int mt = 0; mt < 2; mt++)
                #pragma unroll
                for (int nt = 0; nt < 8; nt++)
                    mma_f16(acc[mt][nt], aa[cur][mt], &bb[cur][nt >> 1][(nt & 1) * 2]);
        }
    }
    __syncthreads();

    float* stage = (float*)smem;          // [128][132]
    #pragma unroll
    for (int mt = 0; mt < 2; mt++)
        #pragma unroll
        for (int nt = 0; nt < 8; nt++) {
            int row = wm * 32 + mt * 16 + (lane >> 2);
            int col = wn * 64 + nt * 8 + (lane & 3) * 2;
            stage[row * 132 + col]           = acc[mt][nt][0];
            stage[row * 132 + col + 1]       = acc[mt][nt][1];
            stage[(row + 8) * 132 + col]     = acc[mt][nt][2];
            stage[(row + 8) * 132 + col + 1] = acc[mt][nt][3];
        }
    __syncthreads();

    #pragma unroll
    for (int i = 0; i < 16; i++) {
        int idx = tid + i * 256;
        int row = idx >> 5;
        int c4  = (idx & 31) * 4;
        float4 bv = *(const float4*)(bias + bn + c4);
        float ox = stage[row * 132 + c4 + 0] + bv.x;
        float oy = stage[row * 132 + c4 + 1] + bv.y;
        float oz = stage[row * 132 + c4 + 2] + bv.z;
        float ow = stage[row * 132 + c4 + 3] + bv.w;
        if constexpr (sizeof(OT) == 4) {
            float4 o = {ox, oy, oz, ow};
            *(float4*)((float*)C + (size_t)(bm + row) * N + bn + c4) = o;
        } else {
            __half h4[4] = {__float2half_rn(ox), __float2half_rn(oy),
                            __float2half_rn(oz), __float2half_rn(ow)};
            *(uint2*)((__half*)C + (size_t)(bm + row) * N + bn + c4) = *(uint2*)h4;
        }
    }
}

// ---------------- local windowed attention (fp16 K/V in smem) ----------------
// Phase A: keys-in-lanes scores. Phase B: 4-rows-per-LDS.128 — lane groups
// (lane>>3) each cover one of 4 consecutive rows, lane&7 covers a 4-dim quad
// of interleaved V; group partials folded with 2 shfl.xor.
#define QT 32
#define KT 96
#define KTV 100
#define KPH 72                        // half stride for Ks/Vs rows (144 B)
#define QPF 68                        // float stride for Qs rows
#define ATTN_SMEM (96 * KPH * 2 + KTV * KPH * 2 + QT * QPF * 4 + 8 * 80 * 4)

__global__ __launch_bounds__(256) void attn_local(
    const __half* __restrict__ qkv, __half* __restrict__ outh)
{
    extern __shared__ char asmem[];
    __half* Ks = (__half*)asmem;                    // [96][72]
    __half* Vs = Ks + 96 * KPH;                     // [100][72] interleaved
    float*  Qs = (float*)(Vs + KTV * KPH);          // [32][68] pre-scaled
    float*  Ps = Qs + QT * QPF;                     // [8][80]

    const int b = blockIdx.z, h = blockIdx.y;
    const int t0 = blockIdx.x * QT;
    const int kbase = t0 - 32;
    const int tid = threadIdx.x;

    #pragma unroll
    for (int i = 0; i < 6; i++) {
        int idx = tid + i * 256;                    // 0..1535
        if (idx < 768) {                            // K
            int row = idx >> 3, c = idx & 7;
            int tk = kbase + row;
            uint4 v = {0u, 0u, 0u, 0u};
            if (tk >= 0 && tk < T_SEQ)
                v = ((const uint4*)(qkv + ((size_t)(b * T_SEQ + tk)) * N_QKV
                                    + D_MODEL + h * HD))[c];
            *(uint4*)(Ks + row * KPH + c * 8) = v;
        } else if (idx < 1152) {                    // V interleaved
            int j = idx - 768;
            int row = j >> 2, c = j & 3;
            int tk = kbase + row;
            uint4 lo = {0u, 0u, 0u, 0u}, hi = {0u, 0u, 0u, 0u};
            if (tk >= 0 && tk < T_SEQ) {
                const __half* base = qkv + ((size_t)(b * T_SEQ + tk)) * N_QKV
                                   + 2 * D_MODEL + h * HD;
                lo = ((const uint4*)base)[c];
                hi = ((const uint4*)(base + 32))[c];
            }
            __half lh[8], hh[8], oo[16];
            memcpy(lh, &lo, 16); memcpy(hh, &hi, 16);
            #pragma unroll
            for (int k = 0; k < 8; k++) { oo[2 * k] = lh[k]; oo[2 * k + 1] = hh[k]; }
            uint4 o0, o1;
            memcpy(&o0, oo, 16); memcpy(&o1, oo + 8, 16);
            __half* dst = Vs + row * KPH + c * 16;
            ((uint4*)dst)[0] = o0; ((uint4*)dst)[1] = o1;
        } else if (idx < 1408) {                    // Q pre-scaled fp32
            int j = idx - 1152;
            int row = j >> 3, c = j & 7;
            uint4 v = ((const uint4*)(qkv + ((size_t)(b * T_SEQ + t0 + row)) * N_QKV
                                      + h * HD))[c];
            __half qh[8]; memcpy(qh, &v, 16);
            float* dst = Qs + row * QPF + c * 8;
            #pragma unroll
            for (int k = 0; k < 8; k++) dst[k] = __half2float(qh[k]) * 0.125f;
        }
    }
    if (tid < 36) {
        int r = tid / 9, c = tid % 9;
        *(uint4*)(Vs + (96 + r) * KPH + c * 8) = make_uint4(0, 0, 0, 0);
    }
    __syncthreads();

    const int warp = tid >> 5, lane = tid & 31;
    const int g  = lane >> 3;       // row group 0..3
    const int kq = lane & 7;        // dim quad 0..7

    #pragma unroll 1
    for (int qq = 0; qq < 4; qq++) {
        const int qi = warp * 4 + qq;
        const int t  = t0 + qi;

        // ---- phase A: scores (keys in lanes), fp16 K ----
        const bool v0 = (t - 32 + lane) >= 0;
        const bool v1 = (t + lane) < T_SEQ;
        float d0 = 0.f, d1 = 0.f;
        const uint4* k0p = (const uint4*)(Ks + (qi + lane) * KPH);
        const uint4* k1p = (const uint4*)(Ks + (qi + 32 + lane) * KPH);
        const float4* qf = (const float4*)(Qs + qi * QPF);
        #pragma unroll
        for (int i = 0; i < 8; i++) {
            uint4 ka = k0p[i], kb = k1p[i];
            float4 qa = qf[2 * i], qb = qf[2 * i + 1];
            const __half2* pa = (const __half2*)&ka;
            const __half2* pb = (const __half2*)&kb;
            float2 a0 = __half22float2(pa[0]), a1 = __half22float2(pa[1]);
            float2 a2 = __half22float2(pa[2]), a3 = __half22float2(pa[3]);
            float2 b0 = __half22float2(pb[0]), b1 = __half22float2(pb[1]);
            float2 b2 = __half22float2(pb[2]), b3 = __half22float2(pb[3]);
            d0 = fmaf(qa.x, a0.x, d0); d0 = fmaf(qa.y, a0.y, d0);
            d0 = fmaf(qa.z, a1.x, d0); d0 = fmaf(qa.w, a1.y, d0);
            d0 = fmaf(qb.x, a2.x, d0); d0 = fmaf(qb.y, a2.y, d0);
            d0 = fmaf(qb.z, a3.x, d0); d0 = fmaf(qb.w, a3.y, d0);
            d1 = fmaf(qa.x, b0.x, d1); d1 = fmaf(qa.y, b0.y, d1);
            d1 = fmaf(qa.z, b1.x, d1); d1 = fmaf(qa.w, b1.y, d1);
            d1 = fmaf(qb.x, b2.x, d1); d1 = fmaf(qb.y, b2.y, d1);
            d1 = fmaf(qb.z, b3.x, d1); d1 = fmaf(qb.w, b3.y, d1);
        }
        float s0 = v0 ? d0 : -1e30f;
        float s1 = v1 ? d1 : -1e30f;

        float part = Qs[qi * QPF + lane]      * __half2float(Ks[(qi + 64) * KPH + lane])
                   + Qs[qi * QPF + lane + 32] * __half2float(Ks[(qi + 64) * KPH + lane + 32]);
        part += __shfl_xor_sync(0xffffffffu, part, 16);
        part += __shfl_xor_sync(0xffffffffu, part, 8);
        part += __shfl_xor_sync(0xffffffffu, part, 4);
        part += __shfl_xor_sync(0xffffffffu, part, 2);
        part += __shfl_xor_sync(0xffffffffu, part, 1);
        const bool v2 = (t + 32) < T_SEQ;
        float s2 = (lane == 0 && v2) ? part : -1e30f;

        // ---- softmax ----
        float m = fmaxf(fmaxf(s0, s1), s2);
        m = fmaxf(m, __shfl_xor_sync(0xffffffffu, m, 16));
        m = fmaxf(m, __shfl_xor_sync(0xffffffffu, m, 8));
        m = fmaxf(m, __shfl_xor_sync(0xffffffffu, m, 4));
        m = fmaxf(m, __shfl_xor_sync(0xffffffffu, m, 2));
        m = fmaxf(m, __shfl_xor_sync(0xffffffffu, m, 1));
        float p0 = __expf(s0 - m);
        float p1 = __expf(s1 - m);
        float p2 = __expf(s2 - m);
        float l = p0 + p1 + p2;
        l += __shfl_xor_sync(0xffffffffu, l, 16);
        l += __shfl_xor_sync(0xffffffffu, l, 8);
        l += __shfl_xor_sync(0xffffffffu, l, 4);
        l += __shfl_xor_sync(0xffffffffu, l, 2);
        l += __shfl_xor_sync(0xffffffffu, l, 1);
        float inv = 1.f / l;

        float* pw = &Ps[warp * 80];
        pw[lane]      = p0 * inv;
        pw[lane + 32] = p1 * inv;
        if (lane < 4) pw[64 + lane] = (lane == 0) ? p2 * inv : 0.f;
        __syncwarp();

        // ---- phase B: 4 rows per LDS.128, groups fold via shfl ----
        float av[8];
        #pragma unroll
        for (int i = 0; i < 8; i++) av[i] = 0.f;
        const __half* vq = Vs + (qi + g) * KPH + kq * 8;
        #pragma unroll
        for (int jb = 0; jb < 17; jb++) {
            float p = pw[jb * 4 + g];
            uint4 v = *(const uint4*)(vq + jb * 4 * KPH);
            const __half2* ph = (const __half2*)&v;
            float2 f0 = __half22float2(ph[0]);
            float2 f1 = __half22float2(ph[1]);
            float2 f2 = __half22float2(ph[2]);
            float2 f3 = __half22float2(ph[3]);
            av[0] = fmaf(p, f0.x, av[0]); av[4] = fmaf(p, f0.y, av[4]);
            av[1] = fmaf(p, f1.x, av[1]); av[5] = fmaf(p, f1.y, av[5]);
            av[2] = fmaf(p, f2.x, av[2]); av[6] = fmaf(p, f2.y, av[6]);
            av[3] = fmaf(p, f3.x, av[3]); av[7] = fmaf(p, f3.y, av[7]);
        }
        #pragma unroll
        for (int i = 0; i < 8; i++) {
            av[i] += __shfl_xor_sync(0xffffffffu, av[i], 8);
            av[i] += __shfl_xor_sync(0xffffffffu, av[i], 16);
        }

        size_t off = ((size_t)(b * T_SEQ + t)) * D_MODEL + h * HD;
        if (g == 0) {
            __half h4[4] = {__float2half_rn(av[0]), __float2half_rn(av[1]),
                            __float2half_rn(av[2]), __float2half_rn(av[3])};
            *(uint2*)(outh + off + kq * 4) = *(uint2*)h4;
        } else if (g == 2) {
            __half h4[4] = {__float2half_rn(av[4]), __float2half_rn(av[5]),
                            __float2half_rn(av[6]), __float2half_rn(av[7])};
            *(uint2*)(outh + off + 32 + kq * 4) = *(uint2*)h4;
        }
        __syncwarp();
    }
}

// ---------------------------------------------------------------------------
extern "C" void kernel_launch(void* const* d_in, const int* in_sizes, int n_in,
                              void* d_out, int out_size)
{
    const float* x    = (const float*)d_in[0];
    const float* Wqkv = (const float*)d_in[1];
    const float* bqkv = (const float*)d_in[2];
    const float* Wout = (const float*)d_in[3];
    const float* bout = (const float*)d_in[4];
    float* out = (float*)d_out;

    __half *qkvh, *xh, *wq, *wo, *ah;
    cudaGetSymbolAddress((void**)&qkvh, g_qkvh);
    cudaGetSymbolAddress((void**)&xh, g_xh);
    cudaGetSymbolAddress((void**)&wq, g_wq);
    cudaGetSymbolAddress((void**)&wo, g_wo);
    cudaGetSymbolAddress((void**)&ah, g_ah);

    cudaFuncSetAttribute(gemm_hmma<__half>, cudaFuncAttributeMaxDynamicSharedMemorySize, SMEM_BYTES);
    cudaFuncSetAttribute(gemm_hmma<float>,  cudaFuncAttributeMaxDynamicSharedMemorySize, SMEM_BYTES);
    cudaFuncSetAttribute(attn_local, cudaFuncAttributeMaxDynamicSharedMemorySize, ATTN_SMEM);

    {
        int total = NX4 + NWQ4 + NWO4;
        conv_all<<<(total + 255) / 256, 256>>>(x, Wqkv, Wout, xh, wq, wo);
    }

    gemm_hmma<__half><<<dim3(N_QKV / 128, M_TOT / 128), 256, SMEM_BYTES>>>(
        xh, wq, bqkv, qkvh, N_QKV);

    attn_local<<<dim3(T_SEQ / QT, NH, BATCH), 256, ATTN_SMEM>>>(qkvh, ah);

    gemm_hmma<float><<<dim3(D_MODEL / 128, M_TOT / 128), 256, SMEM_BYTES>>>(
        ah, wo, bout, out, D_MODEL);
}